// round 2
// baseline (speedup 1.0000x reference)
#include <cuda_runtime.h>

#define B_   16
#define CIN  512
#define COUT 512
#define HS   36
#define WS   36
#define HO   38   // conv output spatial

// ---------------- device scratch (no allocation allowed) ----------------
__device__ float g_sn[B_ * CIN];          // modulated+normalized styles
__device__ float g_bb[B_ * COUT];         // message-modulated bias
__device__ float g_g[B_ * COUT];          // wscale*d*input_gain per (b,o)
__device__ float g_wscale[COUT];
__device__ float g_rawsq[COUT * CIN];     // sum_k weight^2 per (o,i)
__device__ float g_a[(size_t)B_ * COUT * HO * HO];  // conv out + bias (47MB)

__inline__ __device__ float warpReduceSum(float v) {
    #pragma unroll
    for (int off = 16; off; off >>= 1) v += __shfl_xor_sync(0xffffffffu, v, off);
    return v;
}

// ---------------- K1: styles s, normalized sn, modulated bias bb --------
// grid=16 (b), block=512
__global__ void k1_style(const float* __restrict__ w, const float* __restrict__ msg,
                         const float* __restrict__ aw, const float* __restrict__ ab,
                         const float* __restrict__ bias, const float* __restrict__ msw,
                         const float* __restrict__ mbw) {
    int b = blockIdx.x;
    __shared__ float wsh[CIN];
    __shared__ float msh[64];
    __shared__ float ssh[CIN];
    __shared__ float red[16];
    int tid = threadIdx.x;
    wsh[tid] = w[b * CIN + tid];
    if (tid < 64) msh[tid] = msg[b * 64 + tid];
    __syncthreads();
    int warp = tid >> 5, lane = tid & 31;
    // warp per output index (coalesced reads of affine_weight rows)
    #pragma unroll 1
    for (int ii = 0; ii < 32; ii++) {
        int i = warp * 32 + ii;
        const float* ar = aw + (size_t)i * CIN;
        float acc = 0.f;
        for (int j = lane; j < CIN; j += 32) acc += wsh[j] * ar[j];
        float accm = 0.f;
        for (int m = lane; m < 64; m += 32) accm += msh[m] * msw[m * CIN + i];
        float v = warpReduceSum(acc + 0.01f * accm);
        if (lane == 0) ssh[i] = v + ab[i];
    }
    __syncthreads();
    float sv = ssh[tid];
    float ss = warpReduceSum(sv * sv);
    if (lane == 0) red[warp] = ss;
    __syncthreads();
    if (warp == 0) {
        float t = (lane < 16) ? red[lane] : 0.f;
        t = warpReduceSum(t);
        if (lane == 0) red[0] = t;
    }
    __syncthreads();
    g_sn[b * CIN + tid] = sv * rsqrtf(red[0] * (1.f / CIN));
    float bacc = 0.f;
    #pragma unroll 8
    for (int m = 0; m < 64; m++) bacc += msh[m] * mbw[m * COUT + tid];
    g_bb[b * COUT + tid] = bias[tid] + 0.01f * bacc;
}

// ---------------- K2: weight norms ----------------
// grid=512 (o), block=256
__global__ void k2_wnorm(const float* __restrict__ weight) {
    int o = blockIdx.x, tid = threadIdx.x;
    float tot = 0.f;
    for (int i = tid; i < CIN; i += 256) {
        const float* wp = weight + ((size_t)o * CIN + i) * 9;
        float sq = 0.f;
        #pragma unroll
        for (int k = 0; k < 9; k++) sq += wp[k] * wp[k];
        g_rawsq[o * CIN + i] = sq;
        tot += sq;
    }
    __shared__ float red[8];
    int warp = tid >> 5, lane = tid & 31;
    tot = warpReduceSum(tot);
    if (lane == 0) red[warp] = tot;
    __syncthreads();
    if (warp == 0) {
        float t = (lane < 8) ? red[lane] : 0.f;
        t = warpReduceSum(t);
        if (lane == 0) g_wscale[o] = rsqrtf(t * (1.f / (CIN * 9)));
    }
}

// ---------------- K3: demod scale g[b,o] ----------------
// grid=(512, 16) -> (o, b), block=128
__global__ void k3_demod(const float* __restrict__ mag) {
    int o = blockIdx.x, b = blockIdx.y, tid = threadIdx.x;
    float acc = 0.f;
    for (int i = tid; i < CIN; i += 128) {
        float s = g_sn[b * CIN + i];
        acc += g_rawsq[o * CIN + i] * s * s;
    }
    __shared__ float red[4];
    int warp = tid >> 5, lane = tid & 31;
    acc = warpReduceSum(acc);
    if (lane == 0) red[warp] = acc;
    __syncthreads();
    if (tid == 0) {
        float t = red[0] + red[1] + red[2] + red[3];
        float wsc = g_wscale[o];
        float d = rsqrtf(wsc * wsc * t + 1e-8f);
        g_g[b * COUT + o] = d * wsc * rsqrtf(mag[0]);
    }
}

// ---------------- K4: shared-weight 3x3 conv, pad=2 -> 38x38 ----------------
// grid=(64, 16) -> (o-tile of 8, b), block=256
// thread micro-tile: 2 rows x 3 cols for 8 output channels (48 accumulators)
__global__ __launch_bounds__(256) void k4_conv(const float* __restrict__ x,
                                               const float* __restrict__ weight) {
    const int b = blockIdx.y;
    const int o0 = blockIdx.x * 8;
    __shared__ float xs[4 * 40 * 44];   // 4 channels, padded 40x44 (zero halo)
    __shared__ float ws[8 * 4 * 9];
    __shared__ float sns[4];
    int tid = threadIdx.x;
    for (int i = tid; i < 4 * 40 * 44; i += 256) xs[i] = 0.f;

    float acc[8][6];
    #pragma unroll
    for (int a = 0; a < 8; a++)
        #pragma unroll
        for (int j = 0; j < 6; j++) acc[a][j] = 0.f;

    int tr = tid / 13, tc = tid - tr * 13;   // tr:0..18 row pair, tc:0..12 col triple
    bool active = (tid < 247);
    const float* xb = x + (size_t)b * CIN * HS * WS;

    for (int cc = 0; cc < CIN; cc += 4) {
        __syncthreads();
        if (tid < 4) sns[tid] = g_sn[b * CIN + cc + tid];
        for (int e = tid; e < 8 * 4 * 9; e += 256) {
            int oo = e / 36, rem = e - oo * 36;
            ws[e] = weight[((size_t)(o0 + oo) * CIN + cc + (rem / 9)) * 9 + (rem % 9)];
        }
        __syncthreads();
        for (int e = tid; e < 4 * HS * WS; e += 256) {
            int c = e / (HS * WS);
            int rem = e - c * (HS * WS);
            int r = rem / WS, q = rem - r * WS;
            xs[c * 1760 + (r + 2) * 44 + (q + 2)] =
                xb[(size_t)(cc + c) * HS * WS + rem] * sns[c];
        }
        __syncthreads();
        if (active) {
            #pragma unroll
            for (int c = 0; c < 4; c++) {
                float xr[4][5];
                #pragma unroll
                for (int dr = 0; dr < 4; dr++)
                    #pragma unroll
                    for (int dc = 0; dc < 5; dc++)
                        xr[dr][dc] = xs[c * 1760 + (2 * tr + dr) * 44 + (3 * tc + dc)];
                #pragma unroll
                for (int oo = 0; oo < 8; oo++) {
                    const float* wp = &ws[(oo * 4 + c) * 9];
                    #pragma unroll
                    for (int ky = 0; ky < 3; ky++)
                        #pragma unroll
                        for (int kx = 0; kx < 3; kx++) {
                            float wv = wp[ky * 3 + kx];
                            #pragma unroll
                            for (int ry = 0; ry < 2; ry++)
                                #pragma unroll
                                for (int cx = 0; cx < 3; cx++)
                                    acc[oo][ry * 3 + cx] += xr[ry + ky][cx + kx] * wv;
                        }
                }
            }
        }
    }
    if (active) {
        #pragma unroll
        for (int oo = 0; oo < 8; oo++) {
            int o = o0 + oo;
            float gg = g_g[b * COUT + o];
            float bb = g_bb[b * COUT + o];
            float* ap = g_a + ((size_t)b * COUT + o) * HO * HO;
            #pragma unroll
            for (int ry = 0; ry < 2; ry++) {
                int r = 2 * tr + ry;
                #pragma unroll
                for (int cx = 0; cx < 3; cx++) {
                    int q = 3 * tc + cx;
                    if (q < HO) ap[r * HO + q] = acc[oo][ry * 3 + cx] * gg + bb;
                }
            }
        }
    }
}

// ---------------- K5: fused filtered_lrelu ----------------
// grid = 16*512 maps, block=256. Stages in smem:
//  Apad[46][38] (conv out, row-shift +4, zero pad) -> vertical up Vpad[82][46]
//  -> horizontal up + lrelu*sqrt2 + clamp -> Z[82][82]
//  -> vertical down T[36][82] (aliases Apad/Vpad, both dead) -> horizontal down -> out
#define SB_APAD 0
#define SB_VPAD (46 * 38)                     // 1748
#define SB_Z    (46 * 38 + 82 * 46)           // 5520
#define SB_FU   (46 * 38 + 82 * 46 + 82 * 82) // 12244
#define SB_FD   (SB_FU + 12)
#define SB_TOT  (SB_FD + 12)                  // 12268 floats = 49072 B (< 48KB static limit)

__global__ __launch_bounds__(256) void k5_flrelu(const float* __restrict__ fup,
                                                 const float* __restrict__ fdn,
                                                 float* __restrict__ out) {
    const int map = blockIdx.x;
    __shared__ float sb[SB_TOT];
    float* Apad = sb + SB_APAD;   // 46 x 38
    float* Vpad = sb + SB_VPAD;   // 82 x 46
    float* Z    = sb + SB_Z;      // 82 x 82
    float* T    = sb;             // 36 x 82 (aliases Apad+Vpad)
    float* fu   = sb + SB_FU;
    float* fd   = sb + SB_FD;
    int tid = threadIdx.x;
    if (tid < 12) { fu[tid] = fup[tid] * 2.f; fd[tid] = fdn[tid]; }  // gain 4 = 2*2
    for (int i = tid; i < SB_Z; i += 256) sb[i] = 0.f;               // zero Apad+Vpad
    __syncthreads();
    const float* ap = g_a + (size_t)map * HO * HO;
    for (int i = tid; i < HO * HO; i += 256) {
        int r = i / HO, q = i - r * HO;
        Apad[(r + 4) * 38 + q] = ap[i];
    }
    __syncthreads();
    // vertical up: up[u][j] = sum_s f[2s+ph] * a[(u>>1)+1-s][j]
    for (int e = tid; e < 82 * 38; e += 256) {
        int u = e / 38, j = e - u * 38;
        int a0 = u >> 1, ph = u & 1;
        float acc = 0.f;
        #pragma unroll
        for (int sg = 0; sg < 6; sg++)
            acc += fu[2 * sg + ph] * Apad[(a0 + 5 - sg) * 38 + j];
        Vpad[u * 46 + (j + 4)] = acc;
    }
    __syncthreads();
    // horizontal up + lrelu + clamp
    for (int e = tid; e < 82 * 82; e += 256) {
        int u = e / 82, xq = e - u * 82;
        int cq = xq >> 1, ph = xq & 1;
        float acc = 0.f;
        #pragma unroll
        for (int sg = 0; sg < 6; sg++)
            acc += fu[2 * sg + ph] * Vpad[u * 46 + (cq + 5 - sg)];
        acc = (acc >= 0.f) ? acc : 0.2f * acc;
        acc *= 1.4142135623730951f;
        acc = fminf(fmaxf(acc, -256.f), 256.f);
        Z[e] = acc;
    }
    __syncthreads();
    // vertical down (decimate by 2): T[r][x] = sum_s fd[s]*Z[2r+11-s][x]
    for (int e = tid; e < 36 * 82; e += 256) {
        int r = e / 82, xq = e - r * 82;
        float acc = 0.f;
        #pragma unroll
        for (int s = 0; s < 12; s++)
            acc += fd[s] * Z[(2 * r + 11 - s) * 82 + xq];
        T[e] = acc;
    }
    __syncthreads();
    // horizontal down
    float* op = out + (size_t)map * 36 * 36;
    for (int e = tid; e < 36 * 36; e += 256) {
        int r = e / 36, c = e - r * 36;
        float acc = 0.f;
        #pragma unroll
        for (int s = 0; s < 12; s++)
            acc += fd[s] * T[r * 82 + (2 * c + 11 - s)];
        op[e] = acc;
    }
}

// ---------------- launch ----------------
extern "C" void kernel_launch(void* const* d_in, const int* in_sizes, int n_in,
                              void* d_out, int out_size) {
    const float* x    = (const float*)d_in[0];
    const float* w    = (const float*)d_in[1];
    const float* msg  = (const float*)d_in[2];
    const float* aw   = (const float*)d_in[3];
    const float* ab   = (const float*)d_in[4];
    const float* wgt  = (const float*)d_in[5];
    const float* bias = (const float*)d_in[6];
    const float* msw  = (const float*)d_in[7];
    const float* mbw  = (const float*)d_in[8];
    const float* fup  = (const float*)d_in[9];
    const float* fdn  = (const float*)d_in[10];
    const float* mag  = (const float*)d_in[11];
    float* out = (float*)d_out;

    k1_style<<<B_, 512>>>(w, msg, aw, ab, bias, msw, mbw);
    k2_wnorm<<<COUT, 256>>>(wgt);
    k3_demod<<<dim3(COUT, B_), 128>>>(mag);
    k4_conv<<<dim3(COUT / 8, B_), 256>>>(x, wgt);
    k5_flrelu<<<B_ * COUT, 256>>>(fup, fdn, out);
}

// round 3
// speedup vs baseline: 1.3877x; 1.3877x over previous
#include <cuda_runtime.h>
#include <stdint.h>

#define B_   16
#define CIN  512
#define COUT 512
#define HS   36
#define WS   36
#define HO   38   // conv output spatial

// ---------------- device scratch (no allocation allowed) ----------------
__device__ float g_sn[B_ * CIN];          // modulated+normalized styles
__device__ float g_bb[B_ * COUT];         // message-modulated bias
__device__ float g_g[B_ * COUT];          // wscale*d*input_gain per (b,o)
__device__ float g_wscale[COUT];
__device__ float g_rawsq[COUT * CIN];     // sum_k weight^2 per (o,i)
__device__ float g_a[(size_t)B_ * COUT * HO * HO];   // conv out + bias (47MB)
__device__ float g_xs[(size_t)B_ * CIN * HS * WS];   // tf32(x*sn) (42.5MB)
__device__ float g_wt[(size_t)COUT * CIN * 9];       // tf32(weight) (9.4MB)

__inline__ __device__ float warpReduceSum(float v) {
    #pragma unroll
    for (int off = 16; off; off >>= 1) v += __shfl_xor_sync(0xffffffffu, v, off);
    return v;
}

__device__ __forceinline__ float to_tf32(float x) {
    uint32_t r;
    asm("cvt.rna.tf32.f32 %0, %1;" : "=r"(r) : "f"(x));
    return __uint_as_float(r);
}

__device__ __forceinline__ void mma_tf32(float c[4], uint32_t a0, uint32_t a1,
                                         uint32_t a2, uint32_t a3,
                                         uint32_t b0, uint32_t b1) {
    asm volatile(
        "mma.sync.aligned.m16n8k8.row.col.f32.tf32.tf32.f32 "
        "{%0,%1,%2,%3}, {%4,%5,%6,%7}, {%8,%9}, {%0,%1,%2,%3};\n"
        : "+f"(c[0]), "+f"(c[1]), "+f"(c[2]), "+f"(c[3])
        : "r"(a0), "r"(a1), "r"(a2), "r"(a3), "r"(b0), "r"(b1));
}

// ---------------- K1: styles s, normalized sn, modulated bias bb --------
__global__ void k1_style(const float* __restrict__ w, const float* __restrict__ msg,
                         const float* __restrict__ aw, const float* __restrict__ ab,
                         const float* __restrict__ bias, const float* __restrict__ msw,
                         const float* __restrict__ mbw) {
    int b = blockIdx.x;
    __shared__ float wsh[CIN];
    __shared__ float msh[64];
    __shared__ float ssh[CIN];
    __shared__ float red[16];
    int tid = threadIdx.x;
    wsh[tid] = w[b * CIN + tid];
    if (tid < 64) msh[tid] = msg[b * 64 + tid];
    __syncthreads();
    int warp = tid >> 5, lane = tid & 31;
    #pragma unroll 1
    for (int ii = 0; ii < 32; ii++) {
        int i = warp * 32 + ii;
        const float* ar = aw + (size_t)i * CIN;
        float acc = 0.f;
        for (int j = lane; j < CIN; j += 32) acc += wsh[j] * ar[j];
        float accm = 0.f;
        for (int m = lane; m < 64; m += 32) accm += msh[m] * msw[m * CIN + i];
        float v = warpReduceSum(acc + 0.01f * accm);
        if (lane == 0) ssh[i] = v + ab[i];
    }
    __syncthreads();
    float sv = ssh[tid];
    float ss = warpReduceSum(sv * sv);
    if (lane == 0) red[warp] = ss;
    __syncthreads();
    if (warp == 0) {
        float t = (lane < 16) ? red[lane] : 0.f;
        t = warpReduceSum(t);
        if (lane == 0) red[0] = t;
    }
    __syncthreads();
    g_sn[b * CIN + tid] = sv * rsqrtf(red[0] * (1.f / CIN));
    float bacc = 0.f;
    #pragma unroll 8
    for (int m = 0; m < 64; m++) bacc += msh[m] * mbw[m * COUT + tid];
    g_bb[b * COUT + tid] = bias[tid] + 0.01f * bacc;
}

// ---------------- K2: weight norms ----------------
__global__ void k2_wnorm(const float* __restrict__ weight) {
    int o = blockIdx.x, tid = threadIdx.x;
    float tot = 0.f;
    for (int i = tid; i < CIN; i += 256) {
        const float* wp = weight + ((size_t)o * CIN + i) * 9;
        float sq = 0.f;
        #pragma unroll
        for (int k = 0; k < 9; k++) sq += wp[k] * wp[k];
        g_rawsq[o * CIN + i] = sq;
        tot += sq;
    }
    __shared__ float red[8];
    int warp = tid >> 5, lane = tid & 31;
    tot = warpReduceSum(tot);
    if (lane == 0) red[warp] = tot;
    __syncthreads();
    if (warp == 0) {
        float t = (lane < 8) ? red[lane] : 0.f;
        t = warpReduceSum(t);
        if (lane == 0) g_wscale[o] = rsqrtf(t * (1.f / (CIN * 9)));
    }
}

// ---------------- K3: demod scale g[b,o] ----------------
__global__ void k3_demod(const float* __restrict__ mag) {
    int o = blockIdx.x, b = blockIdx.y, tid = threadIdx.x;
    float acc = 0.f;
    for (int i = tid; i < CIN; i += 128) {
        float s = g_sn[b * CIN + i];
        acc += g_rawsq[o * CIN + i] * s * s;
    }
    __shared__ float red[4];
    int warp = tid >> 5, lane = tid & 31;
    acc = warpReduceSum(acc);
    if (lane == 0) red[warp] = acc;
    __syncthreads();
    if (tid == 0) {
        float t = red[0] + red[1] + red[2] + red[3];
        float wsc = g_wscale[o];
        float d = rsqrtf(wsc * wsc * t + 1e-8f);
        g_g[b * COUT + o] = d * wsc * rsqrtf(mag[0]);
    }
}

// ---------------- K0x: xs = tf32(x * sn) ----------------
__global__ void k0_prex(const float* __restrict__ x) {
    size_t e = (size_t)blockIdx.x * 256 + threadIdx.x;
    if (e >= (size_t)B_ * CIN * HS * WS) return;
    int bc = (int)(e / (HS * WS));       // b*512 + c
    g_xs[e] = to_tf32(x[e] * g_sn[bc]);
}

// ---------------- K0w: wt = tf32(weight) ----------------
__global__ void k0_prew(const float* __restrict__ weight) {
    size_t e = (size_t)blockIdx.x * 256 + threadIdx.x;
    if (e >= (size_t)COUT * CIN * 9) return;
    g_wt[e] = to_tf32(weight[e]);
}

// ---------------- K4: tf32 tensor-core conv ----------------
// grid = (8 o-tiles, 10 row-tiles, 16 b), block = 128 (4 warps)
// CTA: 64 Cout x (4 rows x 40 cols). Warp: 32 Cout (2 strips of 16) x 80 px
// (2 rows x 5 col-groups of 8). K: 64 chunks of 8 channels x 9 taps.
__global__ __launch_bounds__(128, 4) void k4_mma() {
    const int b  = blockIdx.z;
    const int o0 = blockIdx.x * 64;
    const int r0 = blockIdx.y * 4;

    __shared__ float xsm[8 * 264];   // [ch][rr*42+col], stride 264 (bank-safe)
    __shared__ float wsm[9 * 512];   // [tap][o 64][k interleaved (k%4)*2+(k/4)]

    const int tid  = threadIdx.x;
    const int lane = tid & 31;
    const int wrp  = tid >> 5;
    const int ob   = (wrp & 1) * 32;    // warp o-offset within CTA
    const int pr0  = (wrp >> 1) * 2;    // warp row-offset within 4-row tile
    const int ln4  = lane >> 2;         // 0..7
    const int lk   = lane & 3;          // 0..3

    // precomputed (rr,col) for the two x-load slots per channel
    const int p0 = tid,        rr0_ = p0 / 42, cl0 = p0 - rr0_ * 42;
    const int p1 = tid + 128;
    const int rr1_ = p1 / 42,  cl1 = p1 - rr1_ * 42;
    const bool hasP1 = (p1 < 252);

    float c[2][10][4];
    #pragma unroll
    for (int s = 0; s < 2; s++)
        #pragma unroll
        for (int f = 0; f < 10; f++)
            #pragma unroll
            for (int j = 0; j < 4; j++) c[s][f][j] = 0.f;

    for (int cc = 0; cc < CIN; cc += 8) {
        __syncthreads();
        // ---- load input tile: 8 ch x 6 rows x 42 cols (zero halo) ----
        {
            const int gr0 = r0 + rr0_ - 2, gq0 = cl0 - 2;
            const int gr1 = r0 + rr1_ - 2, gq1 = cl1 - 2;
            const bool v0 = ((unsigned)gr0 < HS) && ((unsigned)gq0 < WS);
            const bool v1 = hasP1 && ((unsigned)gr1 < HS) && ((unsigned)gq1 < WS);
            #pragma unroll
            for (int ch = 0; ch < 8; ch++) {
                const float* src = g_xs + ((size_t)(b * CIN + cc + ch)) * (HS * WS);
                xsm[ch * 264 + p0] = v0 ? src[gr0 * WS + gq0] : 0.f;
                if (hasP1) xsm[ch * 264 + p1] = v1 ? src[gr1 * WS + gq1] : 0.f;
            }
        }
        // ---- load weight tile: 64 o x 8 k x 9 taps ----
        {
            int o = tid / 72, j = tid - o * 72;
            const float* wsrc = g_wt + (size_t)o0 * (CIN * 9) + cc * 9;
            #pragma unroll 1
            for (int it = 0; it < 36; it++) {
                float v = wsrc[(size_t)o * (CIN * 9) + j];
                int k = j / 9, tap = j - k * 9;
                wsm[tap * 512 + o * 8 + ((k & 3) * 2 + (k >> 2))] = v;
                o += 1; j += 56;
                if (j >= 72) { j -= 72; o += 1; }
            }
        }
        __syncthreads();

        // ---- compute: 9 taps x 10 frags x 2 o-strips ----
        #pragma unroll
        for (int ky = 0; ky < 3; ky++) {
            #pragma unroll
            for (int kx = 0; kx < 3; kx++) {
                const int tap = ky * 3 + kx;
                uint2 a_lo[2], a_hi[2];
                #pragma unroll
                for (int s = 0; s < 2; s++) {
                    const float* wp = wsm + tap * 512 + (ob + s * 16 + ln4) * 8 + lk * 2;
                    a_lo[s] = *(const uint2*)wp;          // rows +0: (a0, a2)
                    a_hi[s] = *(const uint2*)(wp + 64);   // rows +8: (a1, a3)
                }
                #pragma unroll
                for (int f = 0; f < 10; f++) {
                    const int pr = pr0 + (f >= 5 ? 1 : 0);
                    const int cg = (f >= 5 ? f - 5 : f);
                    const int idx = (pr + ky) * 42 + cg * 8 + ln4 + kx;
                    uint32_t b0 = __float_as_uint(xsm[lk * 264 + idx]);
                    uint32_t b1 = __float_as_uint(xsm[(lk + 4) * 264 + idx]);
                    mma_tf32(c[0][f], a_lo[0].x, a_hi[0].x, a_lo[0].y, a_hi[0].y, b0, b1);
                    mma_tf32(c[1][f], a_lo[1].x, a_hi[1].x, a_lo[1].y, a_hi[1].y, b0, b1);
                }
            }
        }
    }

    // ---- epilogue: scale + bias, store to g_a ----
    const int n0 = lk * 2;
    #pragma unroll
    for (int s = 0; s < 2; s++) {
        #pragma unroll
        for (int rh = 0; rh < 2; rh++) {
            const int o = o0 + ob + s * 16 + ln4 + rh * 8;
            const float gg = g_g[b * COUT + o];
            const float bb = g_bb[b * COUT + o];
            float* abase = g_a + ((size_t)(b * COUT + o)) * (HO * HO);
            #pragma unroll
            for (int f = 0; f < 10; f++) {
                const int r = r0 + pr0 + (f >= 5 ? 1 : 0);
                if (r >= HO) continue;
                const int cg = (f >= 5 ? f - 5 : f);
                const int q = cg * 8 + n0;
                float* ap = abase + r * HO;
                float v0 = c[s][f][rh * 2 + 0] * gg + bb;
                float v1 = c[s][f][rh * 2 + 1] * gg + bb;
                if (q < HO)     ap[q]     = v0;
                if (q + 1 < HO) ap[q + 1] = v1;
            }
        }
    }
}

// ---------------- K5: fused filtered_lrelu ----------------
#define SB_APAD 0
#define SB_VPAD (46 * 38)                     // 1748
#define SB_Z    (46 * 38 + 82 * 46)           // 5520
#define SB_FU   (46 * 38 + 82 * 46 + 82 * 82) // 12244
#define SB_FD   (SB_FU + 12)
#define SB_TOT  (SB_FD + 12)                  // 12268 floats = 49072 B

__global__ __launch_bounds__(256) void k5_flrelu(const float* __restrict__ fup,
                                                 const float* __restrict__ fdn,
                                                 float* __restrict__ out) {
    const int map = blockIdx.x;
    __shared__ float sb[SB_TOT];
    float* Apad = sb + SB_APAD;   // 46 x 38
    float* Vpad = sb + SB_VPAD;   // 82 x 46
    float* Z    = sb + SB_Z;      // 82 x 82
    float* T    = sb;             // 36 x 82 (aliases Apad+Vpad)
    float* fu   = sb + SB_FU;
    float* fd   = sb + SB_FD;
    int tid = threadIdx.x;
    if (tid < 12) { fu[tid] = fup[tid] * 2.f; fd[tid] = fdn[tid]; }  // gain 4 = 2*2
    for (int i = tid; i < SB_Z; i += 256) sb[i] = 0.f;
    __syncthreads();
    const float* ap = g_a + (size_t)map * HO * HO;
    for (int i = tid; i < HO * HO; i += 256) {
        int r = i / HO, q = i - r * HO;
        Apad[(r + 4) * 38 + q] = ap[i];
    }
    __syncthreads();
    for (int e = tid; e < 82 * 38; e += 256) {
        int u = e / 38, j = e - u * 38;
        int a0 = u >> 1, ph = u & 1;
        float acc = 0.f;
        #pragma unroll
        for (int sg = 0; sg < 6; sg++)
            acc += fu[2 * sg + ph] * Apad[(a0 + 5 - sg) * 38 + j];
        Vpad[u * 46 + (j + 4)] = acc;
    }
    __syncthreads();
    for (int e = tid; e < 82 * 82; e += 256) {
        int u = e / 82, xq = e - u * 82;
        int cq = xq >> 1, ph = xq & 1;
        float acc = 0.f;
        #pragma unroll
        for (int sg = 0; sg < 6; sg++)
            acc += fu[2 * sg + ph] * Vpad[u * 46 + (cq + 5 - sg)];
        acc = (acc >= 0.f) ? acc : 0.2f * acc;
        acc *= 1.4142135623730951f;
        acc = fminf(fmaxf(acc, -256.f), 256.f);
        Z[e] = acc;
    }
    __syncthreads();
    for (int e = tid; e < 36 * 82; e += 256) {
        int r = e / 82, xq = e - r * 82;
        float acc = 0.f;
        #pragma unroll
        for (int s = 0; s < 12; s++)
            acc += fd[s] * Z[(2 * r + 11 - s) * 82 + xq];
        T[e] = acc;
    }
    __syncthreads();
    float* op = out + (size_t)map * 36 * 36;
    for (int e = tid; e < 36 * 36; e += 256) {
        int r = e / 36, c = e - r * 36;
        float acc = 0.f;
        #pragma unroll
        for (int s = 0; s < 12; s++)
            acc += fd[s] * T[r * 82 + (2 * c + 11 - s)];
        op[e] = acc;
    }
}

// ---------------- launch ----------------
extern "C" void kernel_launch(void* const* d_in, const int* in_sizes, int n_in,
                              void* d_out, int out_size) {
    const float* x    = (const float*)d_in[0];
    const float* w    = (const float*)d_in[1];
    const float* msg  = (const float*)d_in[2];
    const float* aw   = (const float*)d_in[3];
    const float* ab   = (const float*)d_in[4];
    const float* wgt  = (const float*)d_in[5];
    const float* bias = (const float*)d_in[6];
    const float* msw  = (const float*)d_in[7];
    const float* mbw  = (const float*)d_in[8];
    const float* fup  = (const float*)d_in[9];
    const float* fdn  = (const float*)d_in[10];
    const float* mag  = (const float*)d_in[11];
    float* out = (float*)d_out;

    k1_style<<<B_, 512>>>(w, msg, aw, ab, bias, msw, mbw);
    k2_wnorm<<<COUT, 256>>>(wgt);
    k3_demod<<<dim3(COUT, B_), 128>>>(mag);
    {
        size_t nx = (size_t)B_ * CIN * HS * WS;
        k0_prex<<<(unsigned)((nx + 255) / 256), 256>>>(x);
        size_t nw = (size_t)COUT * CIN * 9;
        k0_prew<<<(unsigned)((nw + 255) / 256), 256>>>(wgt);
    }
    k4_mma<<<dim3(COUT / 64, 10, B_), 128>>>();
    k5_flrelu<<<B_ * COUT, 256>>>(fup, fdn, out);
}

// round 6
// speedup vs baseline: 3.0289x; 2.1826x over previous
#include <cuda_runtime.h>
#include <stdint.h>

#define B_   16
#define CIN  512
#define COUT 512
#define HS   36
#define WS   36
#define HO   38   // conv output spatial

#define XP_STRIDE 1764   // padded x map: 42 rows x 42 cols (halo -2..39)
#define XS_S      424    // xsm channel stride (424 % 32 == 8 -> bank-safe)

// ---------------- device scratch (no allocation allowed) ----------------
__device__ float g_sn[B_ * CIN];
__device__ float g_bb[B_ * COUT];
__device__ float g_g[B_ * COUT];
__device__ float g_wscale[COUT];
__device__ float g_rawsq[COUT * CIN];
__device__ float g_a[(size_t)B_ * COUT * HO * HO];        // conv out + bias (47MB)
__device__ float g_xp[(size_t)B_ * CIN * XP_STRIDE];      // padded tf32(x*sn) (58MB)
__device__ float g_wt2[(size_t)COUT * CIN * 9];           // tf32 weights, mma layout (9.4MB)

__inline__ __device__ float warpReduceSum(float v) {
    #pragma unroll
    for (int off = 16; off; off >>= 1) v += __shfl_xor_sync(0xffffffffu, v, off);
    return v;
}

__device__ __forceinline__ float to_tf32(float x) {
    uint32_t r;
    asm("cvt.rna.tf32.f32 %0, %1;" : "=r"(r) : "f"(x));
    return __uint_as_float(r);
}

__device__ __forceinline__ void mma_tf32(float c[4], uint32_t a0, uint32_t a1,
                                         uint32_t a2, uint32_t a3,
                                         uint32_t b0, uint32_t b1) {
    asm volatile(
        "mma.sync.aligned.m16n8k8.row.col.f32.tf32.tf32.f32 "
        "{%0,%1,%2,%3}, {%4,%5,%6,%7}, {%8,%9}, {%0,%1,%2,%3};\n"
        : "+f"(c[0]), "+f"(c[1]), "+f"(c[2]), "+f"(c[3])
        : "r"(a0), "r"(a1), "r"(a2), "r"(a3), "r"(b0), "r"(b1));
}

// ---------------- K1: styles s, normalized sn, modulated bias bb --------
__global__ void k1_style(const float* __restrict__ w, const float* __restrict__ msg,
                         const float* __restrict__ aw, const float* __restrict__ ab,
                         const float* __restrict__ bias, const float* __restrict__ msw,
                         const float* __restrict__ mbw) {
    int b = blockIdx.x;
    __shared__ float wsh[CIN];
    __shared__ float msh[64];
    __shared__ float ssh[CIN];
    __shared__ float red[16];
    int tid = threadIdx.x;
    wsh[tid] = w[b * CIN + tid];
    if (tid < 64) msh[tid] = msg[b * 64 + tid];
    __syncthreads();
    int warp = tid >> 5, lane = tid & 31;
    #pragma unroll 1
    for (int ii = 0; ii < 32; ii++) {
        int i = warp * 32 + ii;
        const float* ar = aw + (size_t)i * CIN;
        float acc = 0.f;
        for (int j = lane; j < CIN; j += 32) acc += wsh[j] * ar[j];
        float accm = 0.f;
        for (int m = lane; m < 64; m += 32) accm += msh[m] * msw[m * CIN + i];
        float v = warpReduceSum(acc + 0.01f * accm);
        if (lane == 0) ssh[i] = v + ab[i];
    }
    __syncthreads();
    float sv = ssh[tid];
    float ss = warpReduceSum(sv * sv);
    if (lane == 0) red[warp] = ss;
    __syncthreads();
    if (warp == 0) {
        float t = (lane < 16) ? red[lane] : 0.f;
        t = warpReduceSum(t);
        if (lane == 0) red[0] = t;
    }
    __syncthreads();
    g_sn[b * CIN + tid] = sv * rsqrtf(red[0] * (1.f / CIN));
    float bacc = 0.f;
    #pragma unroll 8
    for (int m = 0; m < 64; m++) bacc += msh[m] * mbw[m * COUT + tid];
    g_bb[b * COUT + tid] = bias[tid] + 0.01f * bacc;
}

// ---------------- K2: weight norms ----------------
__global__ void k2_wnorm(const float* __restrict__ weight) {
    int o = blockIdx.x, tid = threadIdx.x;
    float tot = 0.f;
    for (int i = tid; i < CIN; i += 256) {
        const float* wp = weight + ((size_t)o * CIN + i) * 9;
        float sq = 0.f;
        #pragma unroll
        for (int k = 0; k < 9; k++) sq += wp[k] * wp[k];
        g_rawsq[o * CIN + i] = sq;
        tot += sq;
    }
    __shared__ float red[8];
    int warp = tid >> 5, lane = tid & 31;
    tot = warpReduceSum(tot);
    if (lane == 0) red[warp] = tot;
    __syncthreads();
    if (warp == 0) {
        float t = (lane < 8) ? red[lane] : 0.f;
        t = warpReduceSum(t);
        if (lane == 0) g_wscale[o] = rsqrtf(t * (1.f / (CIN * 9)));
    }
}

// ---------------- K3: demod scale g[b,o] ----------------
__global__ void k3_demod(const float* __restrict__ mag) {
    int o = blockIdx.x, b = blockIdx.y, tid = threadIdx.x;
    float acc = 0.f;
    for (int i = tid; i < CIN; i += 128) {
        float s = g_sn[b * CIN + i];
        acc += g_rawsq[o * CIN + i] * s * s;
    }
    __shared__ float red[4];
    int warp = tid >> 5, lane = tid & 31;
    acc = warpReduceSum(acc);
    if (lane == 0) red[warp] = acc;
    __syncthreads();
    if (tid == 0) {
        float t = red[0] + red[1] + red[2] + red[3];
        float wsc = g_wscale[o];
        float d = rsqrtf(wsc * wsc * t + 1e-8f);
        g_g[b * COUT + o] = d * wsc * rsqrtf(mag[0]);
    }
}

// ---------------- K0x: padded xs = tf32(x * sn), halo zeros baked in ----
__global__ void k0_prex(const float* __restrict__ x) {
    const size_t N = (size_t)B_ * CIN * XP_STRIDE;
    for (size_t e = (size_t)blockIdx.x * 256 + threadIdx.x; e < N;
         e += (size_t)gridDim.x * 256) {
        int p = (int)(e % XP_STRIDE);
        int map = (int)(e / XP_STRIDE);
        int prg = p / 42, pc = p - prg * 42;
        int gr = prg - 2, gq = pc - 2;
        float v = 0.f;
        if ((unsigned)gr < HS && (unsigned)gq < WS)
            v = to_tf32(x[(size_t)map * (HS * WS) + gr * WS + gq] * g_sn[map]);
        g_xp[e] = v;
    }
}

// ---------------- K0w: weights -> mma-ready layout -------------
// dst[otile][chunk][tap][o_local*8 + kidx], kidx = (k%4)*2 + k/4
__global__ void k0_prew(const float* __restrict__ weight) {
    size_t e = (size_t)blockIdx.x * 256 + threadIdx.x;
    if (e >= (size_t)COUT * CIN * 9) return;
    int tap = (int)(e % 9);
    size_t oi = e / 9;
    int i = (int)(oi % CIN);
    int o = (int)(oi / CIN);
    int k = i & 7;
    int kidx = (k & 3) * 2 + (k >> 2);
    size_t dst = (((size_t)(o >> 6) * 64 + (i >> 3)) * 9 + tap) * 512 + (o & 63) * 8 + kidx;
    g_wt2[dst] = to_tf32(weight[e]);
}

// ---------------- K4: tf32 tensor-core conv ----------------
// grid = (8 o-tiles, 5 row-tiles, 16 b), block = 256 (8 warps)
// CTA: 64 Cout x (8 rows x 40 cols). Warp: 32 Cout (2 strips of 16) x 80 px.
__global__ __launch_bounds__(256, 2) void k4_mma() {
    const int b  = blockIdx.z;
    const int o0 = blockIdx.x * 64;
    const int r0 = blockIdx.y * 8;

    __shared__ float xsm[8 * XS_S];   // [ch][rr*42+col], 10 rows x 42 cols used
    __shared__ float wsm[9 * 512];    // [tap][o*8 + kidx]

    const int tid  = threadIdx.x;
    const int lane = tid & 31;
    const int wrp  = tid >> 5;
    const int ob   = (wrp & 1) * 32;    // warp o-offset
    const int pr0  = (wrp >> 1) * 2;    // warp row-offset (0,2,4,6)
    const int ln4  = lane >> 2;
    const int lk   = lane & 3;

    float c[2][10][4];
    #pragma unroll
    for (int s = 0; s < 2; s++)
        #pragma unroll
        for (int f = 0; f < 10; f++)
            #pragma unroll
            for (int j = 0; j < 4; j++) c[s][f][j] = 0.f;

    const float* xbase = g_xp + (size_t)(b * CIN) * XP_STRIDE + r0 * 42;
    const float4* wbase = (const float4*)g_wt2 + (size_t)(blockIdx.x * 64) * 1152;

    for (int cc = 0; cc < CIN; cc += 8) {
        __syncthreads();
        // ---- x tile: 8 ch x 420 floats, contiguous float2 copies ----
        {
            const float* srcb = xbase + (size_t)cc * XP_STRIDE;
            #pragma unroll
            for (int it = 0; it < 7; it++) {
                int e = tid + it * 256;
                if (e < 1680) {
                    int ch = e / 210, j = e - ch * 210;
                    *(float2*)&xsm[ch * XS_S + 2 * j] =
                        *(const float2*)&srcb[(size_t)ch * XP_STRIDE + 2 * j];
                }
            }
        }
        // ---- weight tile: straight float4 copy (layout matches smem) ----
        {
            const float4* wsrc = wbase + (size_t)(cc >> 3) * 1152;
            float4* wdst = (float4*)wsm;
            #pragma unroll
            for (int it = 0; it < 5; it++) {
                int e = tid + it * 256;
                if (e < 1152) wdst[e] = wsrc[e];
            }
        }
        __syncthreads();

        // ---- compute: 9 taps x 10 frags x 2 o-strips ----
        #pragma unroll
        for (int ky = 0; ky < 3; ky++) {
            #pragma unroll
            for (int kx = 0; kx < 3; kx++) {
                const int tap = ky * 3 + kx;
                uint2 a_lo[2], a_hi[2];
                #pragma unroll
                for (int s = 0; s < 2; s++) {
                    const float* wp = wsm + tap * 512 + (ob + s * 16 + ln4) * 8 + lk * 2;
                    a_lo[s] = *(const uint2*)wp;          // rows +0: (a0, a2)
                    a_hi[s] = *(const uint2*)(wp + 64);   // rows +8: (a1, a3)
                }
                #pragma unroll
                for (int f = 0; f < 10; f++) {
                    const int pr = pr0 + (f >= 5 ? 1 : 0);
                    const int cg = (f >= 5 ? f - 5 : f);
                    const int idx = (pr + ky) * 42 + cg * 8 + ln4 + kx;
                    uint32_t b0 = __float_as_uint(xsm[lk * XS_S + idx]);
                    uint32_t b1 = __float_as_uint(xsm[(lk + 4) * XS_S + idx]);
                    mma_tf32(c[0][f], a_lo[0].x, a_hi[0].x, a_lo[0].y, a_hi[0].y, b0, b1);
                    mma_tf32(c[1][f], a_lo[1].x, a_hi[1].x, a_lo[1].y, a_hi[1].y, b0, b1);
                }
            }
        }
    }

    // ---- epilogue: scale + bias, store to g_a ----
    const int n0 = lk * 2;
    #pragma unroll
    for (int s = 0; s < 2; s++) {
        #pragma unroll
        for (int rh = 0; rh < 2; rh++) {
            const int o = o0 + ob + s * 16 + ln4 + rh * 8;
            const float gg = g_g[b * COUT + o];
            const float bb = g_bb[b * COUT + o];
            float* abase = g_a + ((size_t)(b * COUT + o)) * (HO * HO);
            #pragma unroll
            for (int f = 0; f < 10; f++) {
                const int r = r0 + pr0 + (f >= 5 ? 1 : 0);
                if (r >= HO) continue;
                const int cg = (f >= 5 ? f - 5 : f);
                const int q = cg * 8 + n0;
                float* ap = abase + r * HO;
                float v0 = c[s][f][rh * 2 + 0] * gg + bb;
                float v1 = c[s][f][rh * 2 + 1] * gg + bb;
                if (q < HO)     ap[q]     = v0;
                if (q + 1 < HO) ap[q + 1] = v1;
            }
        }
    }
}

// ---------------- K5: fused filtered_lrelu ----------------
#define SB_APAD 0
#define SB_VPAD (46 * 38)
#define SB_Z    (46 * 38 + 82 * 46)
#define SB_FU   (46 * 38 + 82 * 46 + 82 * 82)
#define SB_FD   (SB_FU + 12)
#define SB_TOT  (SB_FD + 12)   // 12268 floats = 49072 B

__global__ __launch_bounds__(256) void k5_flrelu(const float* __restrict__ fup,
                                                 const float* __restrict__ fdn,
                                                 float* __restrict__ out) {
    const int map = blockIdx.x;
    __shared__ float sb[SB_TOT];
    float* Apad = sb + SB_APAD;
    float* Vpad = sb + SB_VPAD;
    float* Z    = sb + SB_Z;
    float* T    = sb;
    float* fu   = sb + SB_FU;
    float* fd   = sb + SB_FD;
    int tid = threadIdx.x;
    if (tid < 12) { fu[tid] = fup[tid] * 2.f; fd[tid] = fdn[tid]; }
    for (int i = tid; i < SB_Z; i += 256) sb[i] = 0.f;
    __syncthreads();
    const float* ap = g_a + (size_t)map * HO * HO;
    for (int i = tid; i < HO * HO; i += 256) {
        int r = i / HO, q = i - r * HO;
        Apad[(r + 4) * 38 + q] = ap[i];
    }
    __syncthreads();
    for (int e = tid; e < 82 * 38; e += 256) {
        int u = e / 38, j = e - u * 38;
        int a0 = u >> 1, ph = u & 1;
        float acc = 0.f;
        #pragma unroll
        for (int sg = 0; sg < 6; sg++)
            acc += fu[2 * sg + ph] * Apad[(a0 + 5 - sg) * 38 + j];
        Vpad[u * 46 + (j + 4)] = acc;
    }
    __syncthreads();
    for (int e = tid; e < 82 * 82; e += 256) {
        int u = e / 82, xq = e - u * 82;
        int cq = xq >> 1, ph = xq & 1;
        float acc = 0.f;
        #pragma unroll
        for (int sg = 0; sg < 6; sg++)
            acc += fu[2 * sg + ph] * Vpad[u * 46 + (cq + 5 - sg)];
        acc = (acc >= 0.f) ? acc : 0.2f * acc;
        acc *= 1.4142135623730951f;
        acc = fminf(fmaxf(acc, -256.f), 256.f);
        Z[e] = acc;
    }
    __syncthreads();
    for (int e = tid; e < 36 * 82; e += 256) {
        int r = e / 82, xq = e - r * 82;
        float acc = 0.f;
        #pragma unroll
        for (int s = 0; s < 12; s++)
            acc += fd[s] * Z[(2 * r + 11 - s) * 82 + xq];
        T[e] = acc;
    }
    __syncthreads();
    float* op = out + (size_t)map * 36 * 36;
    for (int e = tid; e < 36 * 36; e += 256) {
        int r = e / 36, c = e - r * 36;
        float acc = 0.f;
        #pragma unroll
        for (int s = 0; s < 12; s++)
            acc += fd[s] * T[r * 82 + (2 * c + 11 - s)];
        op[e] = acc;
    }
}

// ---------------- launch ----------------
extern "C" void kernel_launch(void* const* d_in, const int* in_sizes, int n_in,
                              void* d_out, int out_size) {
    const float* x    = (const float*)d_in[0];
    const float* w    = (const float*)d_in[1];
    const float* msg  = (const float*)d_in[2];
    const float* aw   = (const float*)d_in[3];
    const float* ab   = (const float*)d_in[4];
    const float* wgt  = (const float*)d_in[5];
    const float* bias = (const float*)d_in[6];
    const float* msw  = (const float*)d_in[7];
    const float* mbw  = (const float*)d_in[8];
    const float* fup  = (const float*)d_in[9];
    const float* fdn  = (const float*)d_in[10];
    const float* mag  = (const float*)d_in[11];
    float* out = (float*)d_out;

    k1_style<<<B_, 512>>>(w, msg, aw, ab, bias, msw, mbw);
    k2_wnorm<<<COUT, 256>>>(wgt);
    k3_demod<<<dim3(COUT, B_), 128>>>(mag);
    {
        size_t nw = (size_t)COUT * CIN * 9;
        k0_prew<<<(unsigned)((nw + 255) / 256), 256>>>(wgt);
        k0_prex<<<8192, 256>>>(x);
    }
    k4_mma<<<dim3(COUT / 64, 5, B_), 256>>>();
    k5_flrelu<<<B_ * COUT, 256>>>(fup, fdn, out);
}

// round 8
// speedup vs baseline: 3.1903x; 1.0533x over previous
#include <cuda_runtime.h>
#include <stdint.h>

#define B_   16
#define CIN  512
#define COUT 512
#define HS   36
#define WS   36
#define HO   38   // conv output spatial

#define XP_STRIDE 1764   // padded x map: 42 rows x 42 cols (halo -2..39)
#define XS_S      424    // xsm channel stride (424 % 32 == 8 -> bank-safe)
#define XTILE_F   3392   // 8 * XS_S
#define WTILE_F   4608   // 9 * 512
#define STAGE_F   (XTILE_F + WTILE_F)          // 8000 floats per stage
#define K4_SMEM   (2 * STAGE_F * 4)            // 64000 bytes

// ---------------- device scratch (no allocation allowed) ----------------
__device__ float g_sn[B_ * CIN];
__device__ float g_bb[B_ * COUT];
__device__ float g_g[B_ * COUT];
__device__ float g_wscale[COUT];
__device__ float g_rawsq[COUT * CIN];
__device__ float g_a[(size_t)B_ * COUT * HO * HO];        // conv out + bias (47MB)
__device__ float g_xp[(size_t)B_ * CIN * XP_STRIDE];      // padded tf32(x*sn) (58MB)
__device__ float g_wt2[(size_t)COUT * CIN * 9];           // tf32 weights, mma layout (9.4MB)

__inline__ __device__ float warpReduceSum(float v) {
    #pragma unroll
    for (int off = 16; off; off >>= 1) v += __shfl_xor_sync(0xffffffffu, v, off);
    return v;
}

__device__ __forceinline__ float to_tf32(float x) {
    uint32_t r;
    asm("cvt.rna.tf32.f32 %0, %1;" : "=r"(r) : "f"(x));
    return __uint_as_float(r);
}

__device__ __forceinline__ void mma_tf32(float c[4], uint32_t a0, uint32_t a1,
                                         uint32_t a2, uint32_t a3,
                                         uint32_t b0, uint32_t b1) {
    asm volatile(
        "mma.sync.aligned.m16n8k8.row.col.f32.tf32.tf32.f32 "
        "{%0,%1,%2,%3}, {%4,%5,%6,%7}, {%8,%9}, {%0,%1,%2,%3};\n"
        : "+f"(c[0]), "+f"(c[1]), "+f"(c[2]), "+f"(c[3])
        : "r"(a0), "r"(a1), "r"(a2), "r"(a3), "r"(b0), "r"(b1));
}

__device__ __forceinline__ void cp_async8(uint32_t s, const void* g) {
    asm volatile("cp.async.ca.shared.global [%0], [%1], 8;" :: "r"(s), "l"(g));
}
__device__ __forceinline__ void cp_async16(uint32_t s, const void* g) {
    asm volatile("cp.async.cg.shared.global [%0], [%1], 16;" :: "r"(s), "l"(g));
}

// ---------------- K1: styles s, normalized sn, modulated bias bb --------
__global__ void k1_style(const float* __restrict__ w, const float* __restrict__ msg,
                         const float* __restrict__ aw, const float* __restrict__ ab,
                         const float* __restrict__ bias, const float* __restrict__ msw,
                         const float* __restrict__ mbw) {
    int b = blockIdx.x;
    __shared__ float wsh[CIN];
    __shared__ float msh[64];
    __shared__ float ssh[CIN];
    __shared__ float red[16];
    int tid = threadIdx.x;
    wsh[tid] = w[b * CIN + tid];
    if (tid < 64) msh[tid] = msg[b * 64 + tid];
    __syncthreads();
    int warp = tid >> 5, lane = tid & 31;
    #pragma unroll 1
    for (int ii = 0; ii < 32; ii++) {
        int i = warp * 32 + ii;
        const float* ar = aw + (size_t)i * CIN;
        float acc = 0.f;
        for (int j = lane; j < CIN; j += 32) acc += wsh[j] * ar[j];
        float accm = 0.f;
        for (int m = lane; m < 64; m += 32) accm += msh[m] * msw[m * CIN + i];
        float v = warpReduceSum(acc + 0.01f * accm);
        if (lane == 0) ssh[i] = v + ab[i];
    }
    __syncthreads();
    float sv = ssh[tid];
    float ss = warpReduceSum(sv * sv);
    if (lane == 0) red[warp] = ss;
    __syncthreads();
    if (warp == 0) {
        float t = (lane < 16) ? red[lane] : 0.f;
        t = warpReduceSum(t);
        if (lane == 0) red[0] = t;
    }
    __syncthreads();
    g_sn[b * CIN + tid] = sv * rsqrtf(red[0] * (1.f / CIN));
    float bacc = 0.f;
    #pragma unroll 8
    for (int m = 0; m < 64; m++) bacc += msh[m] * mbw[m * COUT + tid];
    g_bb[b * COUT + tid] = bias[tid] + 0.01f * bacc;
}

// ---------------- K2: weight norms ----------------
__global__ void k2_wnorm(const float* __restrict__ weight) {
    int o = blockIdx.x, tid = threadIdx.x;
    float tot = 0.f;
    for (int i = tid; i < CIN; i += 256) {
        const float* wp = weight + ((size_t)o * CIN + i) * 9;
        float sq = 0.f;
        #pragma unroll
        for (int k = 0; k < 9; k++) sq += wp[k] * wp[k];
        g_rawsq[o * CIN + i] = sq;
        tot += sq;
    }
    __shared__ float red[8];
    int warp = tid >> 5, lane = tid & 31;
    tot = warpReduceSum(tot);
    if (lane == 0) red[warp] = tot;
    __syncthreads();
    if (warp == 0) {
        float t = (lane < 8) ? red[lane] : 0.f;
        t = warpReduceSum(t);
        if (lane == 0) g_wscale[o] = rsqrtf(t * (1.f / (CIN * 9)));
    }
}

// ---------------- K3: demod scale g[b,o] ----------------
__global__ void k3_demod(const float* __restrict__ mag) {
    int o = blockIdx.x, b = blockIdx.y, tid = threadIdx.x;
    float acc = 0.f;
    for (int i = tid; i < CIN; i += 128) {
        float s = g_sn[b * CIN + i];
        acc += g_rawsq[o * CIN + i] * s * s;
    }
    __shared__ float red[4];
    int warp = tid >> 5, lane = tid & 31;
    acc = warpReduceSum(acc);
    if (lane == 0) red[warp] = acc;
    __syncthreads();
    if (tid == 0) {
        float t = red[0] + red[1] + red[2] + red[3];
        float wsc = g_wscale[o];
        float d = rsqrtf(wsc * wsc * t + 1e-8f);
        g_g[b * COUT + o] = d * wsc * rsqrtf(mag[0]);
    }
}

// ---------------- K0x: padded xs = tf32(x * sn), halo zeros baked in ----
__global__ void k0_prex(const float* __restrict__ x) {
    const size_t N = (size_t)B_ * CIN * XP_STRIDE;
    for (size_t e = (size_t)blockIdx.x * 256 + threadIdx.x; e < N;
         e += (size_t)gridDim.x * 256) {
        int p = (int)(e % XP_STRIDE);
        int map = (int)(e / XP_STRIDE);
        int prg = p / 42, pc = p - prg * 42;
        int gr = prg - 2, gq = pc - 2;
        float v = 0.f;
        if ((unsigned)gr < HS && (unsigned)gq < WS)
            v = to_tf32(x[(size_t)map * (HS * WS) + gr * WS + gq] * g_sn[map]);
        g_xp[e] = v;
    }
}

// ---------------- K0w: weights -> mma-ready layout -------------
// dst[otile][chunk][tap][o_local*8 + kidx], kidx = (k%4)*2 + k/4
__global__ void k0_prew(const float* __restrict__ weight) {
    size_t e = (size_t)blockIdx.x * 256 + threadIdx.x;
    if (e >= (size_t)COUT * CIN * 9) return;
    int tap = (int)(e % 9);
    size_t oi = e / 9;
    int i = (int)(oi % CIN);
    int o = (int)(oi / CIN);
    int k = i & 7;
    int kidx = (k & 3) * 2 + (k >> 2);
    size_t dst = (((size_t)(o >> 6) * 64 + (i >> 3)) * 9 + tap) * 512 + (o & 63) * 8 + kidx;
    g_wt2[dst] = to_tf32(weight[e]);
}

// ---------------- K4: tf32 tensor-core conv, cp.async double-buffered ----
// grid = (8 o-tiles, 5 row-tiles, 16 b), block = 256 (8 warps)
// CTA: 64 Cout x (8 rows x 40 cols). Warp: 32 Cout (2 strips of 16) x 80 px.
__global__ __launch_bounds__(256, 2) void k4_mma() {
    extern __shared__ float dsm[];
    const int b  = blockIdx.z;
    const int o0 = blockIdx.x * 64;
    const int r0 = blockIdx.y * 8;

    const int tid  = threadIdx.x;
    const int lane = tid & 31;
    const int wrp  = tid >> 5;
    const int ob   = (wrp & 1) * 32;    // warp o-offset
    const int pr0  = (wrp >> 1) * 2;    // warp row-offset (0,2,4,6)
    const int ln4  = lane >> 2;
    const int lk   = lane & 3;

    float c[2][10][4];
    #pragma unroll
    for (int s = 0; s < 2; s++)
        #pragma unroll
        for (int f = 0; f < 10; f++)
            #pragma unroll
            for (int j = 0; j < 4; j++) c[s][f][j] = 0.f;

    const float* xsrc = g_xp + (size_t)(b * CIN) * XP_STRIDE + r0 * 42;
    const float4* wsrc0 = (const float4*)g_wt2 + (size_t)blockIdx.x * 64 * 1152;
    const uint32_t sbase = (uint32_t)__cvta_generic_to_shared(dsm);

    // issue one chunk's tile loads into a stage (async)
    auto issue = [&](int chunk, int stage) {
        const uint32_t xs = sbase + (uint32_t)stage * (STAGE_F * 4);
        const uint32_t wsb = xs + XTILE_F * 4;
        const float* sx = xsrc + (size_t)chunk * 8 * XP_STRIDE;
        #pragma unroll
        for (int it = 0; it < 7; it++) {
            int e = tid + it * 256;
            if (e < 1680) {
                int ch = e / 210, j = e - ch * 210;
                cp_async8(xs + (uint32_t)(ch * XS_S + 2 * j) * 4,
                          sx + (size_t)ch * XP_STRIDE + 2 * j);
            }
        }
        const float4* sw = wsrc0 + (size_t)chunk * 1152;
        #pragma unroll
        for (int it = 0; it < 5; it++) {
            int e = tid + it * 256;
            if (e < 1152) cp_async16(wsb + (uint32_t)e * 16, sw + e);
        }
        asm volatile("cp.async.commit_group;");
    };

    issue(0, 0);
    issue(1, 1);

    for (int i = 0; i < 64; i++) {
        if (i < 62) asm volatile("cp.async.wait_group 1;");
        else        asm volatile("cp.async.wait_group 0;");
        __syncthreads();
        const float* xsm = dsm + (i & 1) * STAGE_F;
        const float* wsm = xsm + XTILE_F;

        // ---- compute: 9 taps x 10 frags x 2 o-strips ----
        #pragma unroll
        for (int ky = 0; ky < 3; ky++) {
            #pragma unroll
            for (int kx = 0; kx < 3; kx++) {
                const int tap = ky * 3 + kx;
                uint2 a_lo[2], a_hi[2];
                #pragma unroll
                for (int s = 0; s < 2; s++) {
                    const float* wp = wsm + tap * 512 + (ob + s * 16 + ln4) * 8 + lk * 2;
                    a_lo[s] = *(const uint2*)wp;          // rows +0: (a0, a2)
                    a_hi[s] = *(const uint2*)(wp + 64);   // rows +8: (a1, a3)
                }
                #pragma unroll
                for (int f = 0; f < 10; f++) {
                    const int pr = pr0 + (f >= 5 ? 1 : 0);
                    const int cg = (f >= 5 ? f - 5 : f);
                    const int idx = (pr + ky) * 42 + cg * 8 + ln4 + kx;
                    uint32_t b0 = __float_as_uint(xsm[lk * XS_S + idx]);
                    uint32_t b1 = __float_as_uint(xsm[(lk + 4) * XS_S + idx]);
                    mma_tf32(c[0][f], a_lo[0].x, a_hi[0].x, a_lo[0].y, a_hi[0].y, b0, b1);
                    mma_tf32(c[1][f], a_lo[1].x, a_hi[1].x, a_lo[1].y, a_hi[1].y, b0, b1);
                }
            }
        }
        __syncthreads();
        if (i + 2 < 64) issue(i + 2, i & 1);
    }

    // ---- epilogue: scale + bias, store to g_a ----
    const int n0 = lk * 2;
    #pragma unroll
    for (int s = 0; s < 2; s++) {
        #pragma unroll
        for (int rh = 0; rh < 2; rh++) {
            const int o = o0 + ob + s * 16 + ln4 + rh * 8;
            const float gg = g_g[b * COUT + o];
            const float bb = g_bb[b * COUT + o];
            float* abase = g_a + ((size_t)(b * COUT + o)) * (HO * HO);
            #pragma unroll
            for (int f = 0; f < 10; f++) {
                const int r = r0 + pr0 + (f >= 5 ? 1 : 0);
                if (r >= HO) continue;
                const int cg = (f >= 5 ? f - 5 : f);
                const int q = cg * 8 + n0;
                float* ap = abase + r * HO;
                float v0 = c[s][f][rh * 2 + 0] * gg + bb;
                float v1 = c[s][f][rh * 2 + 1] * gg + bb;
                if (q < HO)     ap[q]     = v0;
                if (q + 1 < HO) ap[q + 1] = v1;
            }
        }
    }
}

// ---------------- K5: fused filtered_lrelu ----------------
#define SB_APAD 0
#define SB_VPAD (46 * 38)
#define SB_Z    (46 * 38 + 82 * 46)
#define SB_FU   (46 * 38 + 82 * 46 + 82 * 82)
#define SB_FD   (SB_FU + 12)
#define SB_TOT  (SB_FD + 12)   // 12268 floats = 49072 B

__global__ __launch_bounds__(256) void k5_flrelu(const float* __restrict__ fup,
                                                 const float* __restrict__ fdn,
                                                 float* __restrict__ out) {
    const int map = blockIdx.x;
    __shared__ float sb[SB_TOT];
    float* Apad = sb + SB_APAD;
    float* Vpad = sb + SB_VPAD;
    float* Z    = sb + SB_Z;
    float* T    = sb;
    float* fu   = sb + SB_FU;
    float* fd   = sb + SB_FD;
    int tid = threadIdx.x;
    if (tid < 12) { fu[tid] = fup[tid] * 2.f; fd[tid] = fdn[tid]; }
    for (int i = tid; i < SB_Z; i += 256) sb[i] = 0.f;
    __syncthreads();
    const float* ap = g_a + (size_t)map * HO * HO;
    for (int i = tid; i < HO * HO; i += 256) {
        int r = i / HO, q = i - r * HO;
        Apad[(r + 4) * 38 + q] = ap[i];
    }
    __syncthreads();
    for (int e = tid; e < 82 * 38; e += 256) {
        int u = e / 38, j = e - u * 38;
        int a0 = u >> 1, ph = u & 1;
        float acc = 0.f;
        #pragma unroll
        for (int sg = 0; sg < 6; sg++)
            acc += fu[2 * sg + ph] * Apad[(a0 + 5 - sg) * 38 + j];
        Vpad[u * 46 + (j + 4)] = acc;
    }
    __syncthreads();
    for (int e = tid; e < 82 * 82; e += 256) {
        int u = e / 82, xq = e - u * 82;
        int cq = xq >> 1, ph = xq & 1;
        float acc = 0.f;
        #pragma unroll
        for (int sg = 0; sg < 6; sg++)
            acc += fu[2 * sg + ph] * Vpad[u * 46 + (cq + 5 - sg)];
        acc = (acc >= 0.f) ? acc : 0.2f * acc;
        acc *= 1.4142135623730951f;
        acc = fminf(fmaxf(acc, -256.f), 256.f);
        Z[e] = acc;
    }
    __syncthreads();
    for (int e = tid; e < 36 * 82; e += 256) {
        int r = e / 82, xq = e - r * 82;
        float acc = 0.f;
        #pragma unroll
        for (int s = 0; s < 12; s++)
            acc += fd[s] * Z[(2 * r + 11 - s) * 82 + xq];
        T[e] = acc;
    }
    __syncthreads();
    float* op = out + (size_t)map * 36 * 36;
    for (int e = tid; e < 36 * 36; e += 256) {
        int r = e / 36, c = e - r * 36;
        float acc = 0.f;
        #pragma unroll
        for (int s = 0; s < 12; s++)
            acc += fd[s] * T[r * 82 + (2 * c + 11 - s)];
        op[e] = acc;
    }
}

// ---------------- launch ----------------
extern "C" void kernel_launch(void* const* d_in, const int* in_sizes, int n_in,
                              void* d_out, int out_size) {
    const float* x    = (const float*)d_in[0];
    const float* w    = (const float*)d_in[1];
    const float* msg  = (const float*)d_in[2];
    const float* aw   = (const float*)d_in[3];
    const float* ab   = (const float*)d_in[4];
    const float* wgt  = (const float*)d_in[5];
    const float* bias = (const float*)d_in[6];
    const float* msw  = (const float*)d_in[7];
    const float* mbw  = (const float*)d_in[8];
    const float* fup  = (const float*)d_in[9];
    const float* fdn  = (const float*)d_in[10];
    const float* mag  = (const float*)d_in[11];
    float* out = (float*)d_out;

    cudaFuncSetAttribute(k4_mma, cudaFuncAttributeMaxDynamicSharedMemorySize, K4_SMEM);

    k1_style<<<B_, 512>>>(w, msg, aw, ab, bias, msw, mbw);
    k2_wnorm<<<COUT, 256>>>(wgt);
    k3_demod<<<dim3(COUT, B_), 128>>>(mag);
    {
        size_t nw = (size_t)COUT * CIN * 9;
        k0_prew<<<(unsigned)((nw + 255) / 256), 256>>>(wgt);
        k0_prex<<<8192, 256>>>(x);
    }
    k4_mma<<<dim3(COUT / 64, 5, B_), 256, K4_SMEM>>>();
    k5_flrelu<<<B_ * COUT, 256>>>(fup, fdn, out);
}

// round 12
// speedup vs baseline: 4.9458x; 1.5503x over previous
#include <cuda_runtime.h>
#include <cuda_fp16.h>
#include <stdint.h>

#define B_   16
#define CIN  512
#define COUT 512
#define HS   36
#define WS   36
#define HO   38   // conv output spatial

#define XP_STRIDE 1764   // padded x map: 42 rows x 42 cols (halo -2..39), u32(half2) units
#define XS_S      424    // x-tile pair-row stride in u32 (424 % 32 == 8 -> bank-safe)
#define XTILE_U   3392   // 8 pair-rows * XS_S
#define WTILE_U   4608   // 9 taps * 512 (64 o * 8 kpidx)
#define STAGE_U   (XTILE_U + WTILE_U)          // 8000 u32 per stage
#define K4_SMEM   (2 * STAGE_U * 4)            // 64000 bytes

// ---------------- device scratch (no allocation allowed) ----------------
__device__ float g_sn[B_ * CIN];
__device__ float g_bb[B_ * COUT];
__device__ float g_g[B_ * COUT];
__device__ float g_wscale[COUT];
__device__ float g_rawsq[COUT * CIN];
__device__ float g_a[(size_t)B_ * COUT * HO * HO];          // conv out + bias (47MB)
__device__ uint32_t g_xh[(size_t)B_ * 256 * XP_STRIDE];     // half2(x*sn) padded (28.9MB)
__device__ uint32_t g_wh2[(size_t)8 * 32 * 9 * 512];        // half2 weights, mma layout (4.7MB)

__inline__ __device__ float warpReduceSum(float v) {
    #pragma unroll
    for (int off = 16; off; off >>= 1) v += __shfl_xor_sync(0xffffffffu, v, off);
    return v;
}

__device__ __forceinline__ void mma_f16(float c[4], uint32_t a0, uint32_t a1,
                                        uint32_t a2, uint32_t a3,
                                        uint32_t b0, uint32_t b1) {
    asm volatile(
        "mma.sync.aligned.m16n8k16.row.col.f32.f16.f16.f32 "
        "{%0,%1,%2,%3}, {%4,%5,%6,%7}, {%8,%9}, {%0,%1,%2,%3};\n"
        : "+f"(c[0]), "+f"(c[1]), "+f"(c[2]), "+f"(c[3])
        : "r"(a0), "r"(a1), "r"(a2), "r"(a3), "r"(b0), "r"(b1));
}

__device__ __forceinline__ void cp_async16(uint32_t s, const void* g) {
    asm volatile("cp.async.cg.shared.global [%0], [%1], 16;" :: "r"(s), "l"(g));
}

// ---------------- K1: styles s, normalized sn, modulated bias bb --------
__global__ void k1_style(const float* __restrict__ w, const float* __restrict__ msg,
                         const float* __restrict__ aw, const float* __restrict__ ab,
                         const float* __restrict__ bias, const float* __restrict__ msw,
                         const float* __restrict__ mbw) {
    int b = blockIdx.x;
    __shared__ float wsh[CIN];
    __shared__ float msh[64];
    __shared__ float ssh[CIN];
    __shared__ float red[16];
    int tid = threadIdx.x;
    wsh[tid] = w[b * CIN + tid];
    if (tid < 64) msh[tid] = msg[b * 64 + tid];
    __syncthreads();
    int warp = tid >> 5, lane = tid & 31;
    #pragma unroll 1
    for (int ii = 0; ii < 32; ii++) {
        int i = warp * 32 + ii;
        const float* ar = aw + (size_t)i * CIN;
        float acc = 0.f;
        for (int j = lane; j < CIN; j += 32) acc += wsh[j] * ar[j];
        float accm = 0.f;
        for (int m = lane; m < 64; m += 32) accm += msh[m] * msw[m * CIN + i];
        float v = warpReduceSum(acc + 0.01f * accm);
        if (lane == 0) ssh[i] = v + ab[i];
    }
    __syncthreads();
    float sv = ssh[tid];
    float ss = warpReduceSum(sv * sv);
    if (lane == 0) red[warp] = ss;
    __syncthreads();
    if (warp == 0) {
        float t = (lane < 16) ? red[lane] : 0.f;
        t = warpReduceSum(t);
        if (lane == 0) red[0] = t;
    }
    __syncthreads();
    g_sn[b * CIN + tid] = sv * rsqrtf(red[0] * (1.f / CIN));
    float bacc = 0.f;
    #pragma unroll 8
    for (int m = 0; m < 64; m++) bacc += msh[m] * mbw[m * COUT + tid];
    g_bb[b * COUT + tid] = bias[tid] + 0.01f * bacc;
}

// ---------------- K2: weight norms ----------------
__global__ void k2_wnorm(const float* __restrict__ weight) {
    int o = blockIdx.x, tid = threadIdx.x;
    float tot = 0.f;
    for (int i = tid; i < CIN; i += 256) {
        const float* wp = weight + ((size_t)o * CIN + i) * 9;
        float sq = 0.f;
        #pragma unroll
        for (int k = 0; k < 9; k++) sq += wp[k] * wp[k];
        g_rawsq[o * CIN + i] = sq;
        tot += sq;
    }
    __shared__ float red[8];
    int warp = tid >> 5, lane = tid & 31;
    tot = warpReduceSum(tot);
    if (lane == 0) red[warp] = tot;
    __syncthreads();
    if (warp == 0) {
        float t = (lane < 8) ? red[lane] : 0.f;
        t = warpReduceSum(t);
        if (lane == 0) g_wscale[o] = rsqrtf(t * (1.f / (CIN * 9)));
    }
}

// ---------------- K3: demod scale g[b,o] ----------------
__global__ void k3_demod(const float* __restrict__ mag) {
    int o = blockIdx.x, b = blockIdx.y, tid = threadIdx.x;
    float acc = 0.f;
    for (int i = tid; i < CIN; i += 128) {
        float s = g_sn[b * CIN + i];
        acc += g_rawsq[o * CIN + i] * s * s;
    }
    __shared__ float red[4];
    int warp = tid >> 5, lane = tid & 31;
    acc = warpReduceSum(acc);
    if (lane == 0) red[warp] = acc;
    __syncthreads();
    if (tid == 0) {
        float t = red[0] + red[1] + red[2] + red[3];
        float wsc = g_wscale[o];
        float d = rsqrtf(wsc * wsc * t + 1e-8f);
        g_g[b * COUT + o] = d * wsc * rsqrtf(mag[0]);
    }
}

// ---------------- K0x: padded half2(x*sn), halo zeros baked in --------
// g_xh[(b*256+pair)][p], p in 42x42 padded map; pair = channels (2p, 2p+1)
__global__ void k0_prex(const float* __restrict__ x) {
    const size_t N = (size_t)B_ * 256 * XP_STRIDE;
    for (size_t e = (size_t)blockIdx.x * 256 + threadIdx.x; e < N;
         e += (size_t)gridDim.x * 256) {
        int p = (int)(e % XP_STRIDE);
        int mp = (int)(e / XP_STRIDE);
        int b = mp >> 8, pairIdx = mp & 255;
        int c0 = pairIdx * 2;
        int prg = p / 42, pc = p - prg * 42;
        int gr = prg - 2, gq = pc - 2;
        float v0 = 0.f, v1 = 0.f;
        if ((unsigned)gr < HS && (unsigned)gq < WS) {
            size_t sidx = (((size_t)b * CIN + c0) * HS + gr) * WS + gq;
            v0 = x[sidx] * g_sn[b * CIN + c0];
            v1 = x[sidx + (size_t)HS * WS] * g_sn[b * CIN + c0 + 1];
        }
        __half2 h = __floats2half2_rn(v0, v1);
        g_xh[e] = *(uint32_t*)&h;
    }
}

// ---------------- K0w: weights -> half2 mma layout -------------
// dst[ot][chunk][tap][o_local*8 + kpidx], kpidx = (kpl%4)*2 + kpl/4
// kpl = pair-in-chunk (0..7); u32 = half2(w[ch even], w[ch odd])
__global__ void k0_prew(const float* __restrict__ weight) {
    int e = blockIdx.x * 256 + threadIdx.x;
    const int N = COUT * 256 * 9;      // (o, global pair, tap)
    if (e >= N) return;
    int tap = e % 9;
    int r = e / 9;
    int kp = r & 255;                  // global channel pair 0..255
    int o = r >> 8;
    int chunk = kp >> 3, kpl = kp & 7;
    int kpidx = (kpl & 3) * 2 + (kpl >> 2);
    size_t s0 = ((size_t)o * CIN + kp * 2) * 9 + tap;
    __half2 h = __floats2half2_rn(weight[s0], weight[s0 + 9]);
    size_t dst = ((((size_t)(o >> 6) * 32 + chunk) * 9 + tap) * 512) + (o & 63) * 8 + kpidx;
    g_wh2[dst] = *(uint32_t*)&h;
}

// ---------------- K4: fp16 m16n8k16 conv, cp.async double-buffered ----
// grid = (8 o-tiles, 5 row-tiles, 16 b), block = 256 (8 warps)
// CTA: 64 Cout x (8 rows x 40 cols). Warp: 32 Cout (2 strips of 16) x 80 px.
// 32 chunks of 16 channels; 9 taps per chunk.
__global__ __launch_bounds__(256, 2) void k4_mma() {
    extern __shared__ uint32_t dsm[];
    const int b  = blockIdx.z;
    const int o0 = blockIdx.x * 64;
    const int r0 = blockIdx.y * 8;

    const int tid  = threadIdx.x;
    const int lane = tid & 31;
    const int wrp  = tid >> 5;
    const int ob   = (wrp & 1) * 32;    // warp o-offset
    const int pr0  = (wrp >> 1) * 2;    // warp row-offset (0,2,4,6)
    const int ln4  = lane >> 2;
    const int lk   = lane & 3;

    float c[2][10][4];
    #pragma unroll
    for (int s = 0; s < 2; s++)
        #pragma unroll
        for (int f = 0; f < 10; f++)
            #pragma unroll
            for (int j = 0; j < 4; j++) c[s][f][j] = 0.f;

    // x source: pair rows for chunk cc start at global pair b*256 + cc*8; row-tile offset r0
    const uint32_t* xsrc = g_xh + (size_t)(b * 256) * XP_STRIDE + r0 * 42;
    const uint32_t* wsrc0 = g_wh2 + (size_t)blockIdx.x * 32 * 9 * 512;
    const uint32_t sbase = (uint32_t)__cvta_generic_to_shared(dsm);

    auto issue = [&](int chunk, int stage) {
        const uint32_t xs = sbase + (uint32_t)stage * (STAGE_U * 4);
        const uint32_t wsb = xs + XTILE_U * 4;
        const uint32_t* sx = xsrc + (size_t)chunk * 8 * XP_STRIDE;
        // x tile: 8 pair-rows x 420 u32 = 840 float4s
        #pragma unroll
        for (int it = 0; it < 4; it++) {
            int e = tid + it * 256;
            if (e < 840) {
                int pr = e / 105, j = e - pr * 105;
                cp_async16(xs + (uint32_t)(pr * XS_S + 4 * j) * 4,
                           sx + (size_t)pr * XP_STRIDE + 4 * j);
            }
        }
        // w tile: 4608 u32 = 1152 float4s, layout matches smem
        const uint32_t* sw = wsrc0 + (size_t)chunk * (9 * 512);
        #pragma unroll
        for (int it = 0; it < 5; it++) {
            int e = tid + it * 256;
            if (e < 1152) cp_async16(wsb + (uint32_t)e * 16, sw + (size_t)e * 4);
        }
        asm volatile("cp.async.commit_group;");
    };

    issue(0, 0);
    issue(1, 1);

    for (int i = 0; i < 32; i++) {
        if (i < 30) asm volatile("cp.async.wait_group 1;");
        else        asm volatile("cp.async.wait_group 0;");
        __syncthreads();
        const uint32_t* xsm = dsm + (i & 1) * STAGE_U;
        const uint32_t* wsm = xsm + XTILE_U;

        // ---- compute: 9 taps x 10 frags x 2 o-strips, K=16/mma ----
        #pragma unroll
        for (int ky = 0; ky < 3; ky++) {
            #pragma unroll
            for (int kx = 0; kx < 3; kx++) {
                const int tap = ky * 3 + kx;
                uint2 a_lo[2], a_hi[2];
                #pragma unroll
                for (int s = 0; s < 2; s++) {
                    const uint32_t* wp = wsm + tap * 512 + (ob + s * 16 + ln4) * 8 + lk * 2;
                    a_lo[s] = *(const uint2*)wp;          // rows +0: (a0, a2)
                    a_hi[s] = *(const uint2*)(wp + 64);   // rows +8: (a1, a3)
                }
                #pragma unroll
                for (int f = 0; f < 10; f++) {
                    const int pr = pr0 + (f >= 5 ? 1 : 0);
                    const int cg = (f >= 5 ? f - 5 : f);
                    const int idx = (pr + ky) * 42 + cg * 8 + ln4 + kx;
                    uint32_t b0 = xsm[lk * XS_S + idx];          // pairs lk (ch 2lk,2lk+1)
                    uint32_t b1 = xsm[(lk + 4) * XS_S + idx];    // pairs lk+4 (ch 2lk+8,+9)
                    mma_f16(c[0][f], a_lo[0].x, a_hi[0].x, a_lo[0].y, a_hi[0].y, b0, b1);
                    mma_f16(c[1][f], a_lo[1].x, a_hi[1].x, a_lo[1].y, a_hi[1].y, b0, b1);
                }
            }
        }
        __syncthreads();
        if (i + 2 < 32) issue(i + 2, i & 1);
    }

    // ---- epilogue: scale + bias, store to g_a ----
    const int n0 = lk * 2;
    #pragma unroll
    for (int s = 0; s < 2; s++) {
        #pragma unroll
        for (int rh = 0; rh < 2; rh++) {
            const int o = o0 + ob + s * 16 + ln4 + rh * 8;
            const float gg = g_g[b * COUT + o];
            const float bb = g_bb[b * COUT + o];
            float* abase = g_a + ((size_t)(b * COUT + o)) * (HO * HO);
            #pragma unroll
            for (int f = 0; f < 10; f++) {
                const int r = r0 + pr0 + (f >= 5 ? 1 : 0);
                if (r >= HO) continue;
                const int cg = (f >= 5 ? f - 5 : f);
                const int q = cg * 8 + n0;
                float* ap = abase + r * HO;
                float v0 = c[s][f][rh * 2 + 0] * gg + bb;
                float v1 = c[s][f][rh * 2 + 1] * gg + bb;
                if (q < HO)     ap[q]     = v0;
                if (q + 1 < HO) ap[q + 1] = v1;
            }
        }
    }
}

// ---------------- K5: fused filtered_lrelu ----------------
#define SB_APAD 0
#define SB_VPAD (46 * 38)
#define SB_Z    (46 * 38 + 82 * 46)
#define SB_FU   (46 * 38 + 82 * 46 + 82 * 82)
#define SB_FD   (SB_FU + 12)
#define SB_TOT  (SB_FD + 12)   // 12268 floats = 49072 B

__global__ __launch_bounds__(256) void k5_flrelu(const float* __restrict__ fup,
                                                 const float* __restrict__ fdn,
                                                 float* __restrict__ out) {
    const int map = blockIdx.x;
    __shared__ float sb[SB_TOT];
    float* Apad = sb + SB_APAD;
    float* Vpad = sb + SB_VPAD;
    float* Z    = sb + SB_Z;
    float* T    = sb;
    float* fu   = sb + SB_FU;
    float* fd   = sb + SB_FD;
    int tid = threadIdx.x;
    if (tid < 12) { fu[tid] = fup[tid] * 2.f; fd[tid] = fdn[tid]; }
    for (int i = tid; i < SB_Z; i += 256) sb[i] = 0.f;
    __syncthreads();
    const float* ap = g_a + (size_t)map * HO * HO;
    for (int i = tid; i < HO * HO; i += 256) {
        int r = i / HO, q = i - r * HO;
        Apad[(r + 4) * 38 + q] = ap[i];
    }
    __syncthreads();
    for (int e = tid; e < 82 * 38; e += 256) {
        int u = e / 38, j = e - u * 38;
        int a0 = u >> 1, ph = u & 1;
        float acc = 0.f;
        #pragma unroll
        for (int sg = 0; sg < 6; sg++)
            acc += fu[2 * sg + ph] * Apad[(a0 + 5 - sg) * 38 + j];
        Vpad[u * 46 + (j + 4)] = acc;
    }
    __syncthreads();
    for (int e = tid; e < 82 * 82; e += 256) {
        int u = e / 82, xq = e - u * 82;
        int cq = xq >> 1, ph = xq & 1;
        float acc = 0.f;
        #pragma unroll
        for (int sg = 0; sg < 6; sg++)
            acc += fu[2 * sg + ph] * Vpad[u * 46 + (cq + 5 - sg)];
        acc = (acc >= 0.f) ? acc : 0.2f * acc;
        acc *= 1.4142135623730951f;
        acc = fminf(fmaxf(acc, -256.f), 256.f);
        Z[e] = acc;
    }
    __syncthreads();
    for (int e = tid; e < 36 * 82; e += 256) {
        int r = e / 82, xq = e - r * 82;
        float acc = 0.f;
        #pragma unroll
        for (int s = 0; s < 12; s++)
            acc += fd[s] * Z[(2 * r + 11 - s) * 82 + xq];
        T[e] = acc;
    }
    __syncthreads();
    float* op = out + (size_t)map * 36 * 36;
    for (int e = tid; e < 36 * 36; e += 256) {
        int r = e / 36, c = e - r * 36;
        float acc = 0.f;
        #pragma unroll
        for (int s = 0; s < 12; s++)
            acc += fd[s] * T[r * 82 + (2 * c + 11 - s)];
        op[e] = acc;
    }
}

// ---------------- launch ----------------
extern "C" void kernel_launch(void* const* d_in, const int* in_sizes, int n_in,
                              void* d_out, int out_size) {
    const float* x    = (const float*)d_in[0];
    const float* w    = (const float*)d_in[1];
    const float* msg  = (const float*)d_in[2];
    const float* aw   = (const float*)d_in[3];
    const float* ab   = (const float*)d_in[4];
    const float* wgt  = (const float*)d_in[5];
    const float* bias = (const float*)d_in[6];
    const float* msw  = (const float*)d_in[7];
    const float* mbw  = (const float*)d_in[8];
    const float* fup  = (const float*)d_in[9];
    const float* fdn  = (const float*)d_in[10];
    const float* mag  = (const float*)d_in[11];
    float* out = (float*)d_out;

    cudaFuncSetAttribute(k4_mma, cudaFuncAttributeMaxDynamicSharedMemorySize, K4_SMEM);

    k1_style<<<B_, 512>>>(w, msg, aw, ab, bias, msw, mbw);
    k2_wnorm<<<COUT, 256>>>(wgt);
    k3_demod<<<dim3(COUT, B_), 128>>>(mag);
    {
        int nw = COUT * 256 * 9;
        k0_prew<<<(nw + 255) / 256, 256>>>(wgt);
        k0_prex<<<8192, 256>>>(x);
    }
    k4_mma<<<dim3(COUT / 64, 5, B_), 256, K4_SMEM>>>();
    k5_flrelu<<<B_ * COUT, 256>>>(fup, fdn, out);
}

// round 14
// speedup vs baseline: 5.2595x; 1.0634x over previous
#include <cuda_runtime.h>
#include <cuda_fp16.h>
#include <stdint.h>

#define B_   16
#define CIN  512
#define COUT 512
#define HS   36
#define WS   36
#define HO   38   // conv output spatial

#define XP_STRIDE 1764   // padded x map: 42 rows x 42 cols (halo -2..39), u32(half2) units
#define XT_S      264    // k4 x-tile pair-row stride in u32 (264 % 32 == 8 -> bank-safe)
#define XTILE_U   2112   // 8 pair-rows * XT_S (6 rows x 42 used per pair-row)
#define WTILE_U   4608   // 9 taps * 512 (64 o * 8 kpidx)
#define STAGE_U   (XTILE_U + WTILE_U)          // 6720 u32 per stage
#define K4_SMEM   (2 * STAGE_U * 4)            // 53760 bytes

// ---------------- device scratch (no allocation allowed) ----------------
__device__ float g_sn[B_ * CIN];
__device__ float g_bb[B_ * COUT];
__device__ float g_g[B_ * COUT];
__device__ float g_wscale[COUT];
__device__ float g_rawsq[COUT * CIN];
__device__ float g_a[(size_t)B_ * COUT * HO * HO];          // conv out + bias (47MB)
__device__ uint32_t g_xh[(size_t)B_ * 256 * XP_STRIDE];     // half2(x*sn) padded (28.9MB)
__device__ uint32_t g_wh2[(size_t)8 * 32 * 9 * 512];        // half2 weights, mma layout (4.7MB)

__inline__ __device__ float warpReduceSum(float v) {
    #pragma unroll
    for (int off = 16; off; off >>= 1) v += __shfl_xor_sync(0xffffffffu, v, off);
    return v;
}

__device__ __forceinline__ void mma_f16(float c[4], uint32_t a0, uint32_t a1,
                                        uint32_t a2, uint32_t a3,
                                        uint32_t b0, uint32_t b1) {
    asm volatile(
        "mma.sync.aligned.m16n8k16.row.col.f32.f16.f16.f32 "
        "{%0,%1,%2,%3}, {%4,%5,%6,%7}, {%8,%9}, {%0,%1,%2,%3};\n"
        : "+f"(c[0]), "+f"(c[1]), "+f"(c[2]), "+f"(c[3])
        : "r"(a0), "r"(a1), "r"(a2), "r"(a3), "r"(b0), "r"(b1));
}

__device__ __forceinline__ void cp_async16(uint32_t s, const void* g) {
    asm volatile("cp.async.cg.shared.global [%0], [%1], 16;" :: "r"(s), "l"(g));
}

// ---------------- K1: styles s, normalized sn, modulated bias bb --------
__global__ void k1_style(const float* __restrict__ w, const float* __restrict__ msg,
                         const float* __restrict__ aw, const float* __restrict__ ab,
                         const float* __restrict__ bias, const float* __restrict__ msw,
                         const float* __restrict__ mbw) {
    int b = blockIdx.x;
    __shared__ float wsh[CIN];
    __shared__ float msh[64];
    __shared__ float ssh[CIN];
    __shared__ float red[16];
    int tid = threadIdx.x;
    wsh[tid] = w[b * CIN + tid];
    if (tid < 64) msh[tid] = msg[b * 64 + tid];
    __syncthreads();
    int warp = tid >> 5, lane = tid & 31;
    #pragma unroll 1
    for (int ii = 0; ii < 32; ii++) {
        int i = warp * 32 + ii;
        const float* ar = aw + (size_t)i * CIN;
        float acc = 0.f;
        for (int j = lane; j < CIN; j += 32) acc += wsh[j] * ar[j];
        float accm = 0.f;
        for (int m = lane; m < 64; m += 32) accm += msh[m] * msw[m * CIN + i];
        float v = warpReduceSum(acc + 0.01f * accm);
        if (lane == 0) ssh[i] = v + ab[i];
    }
    __syncthreads();
    float sv = ssh[tid];
    float ss = warpReduceSum(sv * sv);
    if (lane == 0) red[warp] = ss;
    __syncthreads();
    if (warp == 0) {
        float t = (lane < 16) ? red[lane] : 0.f;
        t = warpReduceSum(t);
        if (lane == 0) red[0] = t;
    }
    __syncthreads();
    g_sn[b * CIN + tid] = sv * rsqrtf(red[0] * (1.f / CIN));
    float bacc = 0.f;
    #pragma unroll 8
    for (int m = 0; m < 64; m++) bacc += msh[m] * mbw[m * COUT + tid];
    g_bb[b * COUT + tid] = bias[tid] + 0.01f * bacc;
}

// ---------------- K2: weight norms ----------------
__global__ void k2_wnorm(const float* __restrict__ weight) {
    int o = blockIdx.x, tid = threadIdx.x;
    float tot = 0.f;
    for (int i = tid; i < CIN; i += 256) {
        const float* wp = weight + ((size_t)o * CIN + i) * 9;
        float sq = 0.f;
        #pragma unroll
        for (int k = 0; k < 9; k++) sq += wp[k] * wp[k];
        g_rawsq[o * CIN + i] = sq;
        tot += sq;
    }
    __shared__ float red[8];
    int warp = tid >> 5, lane = tid & 31;
    tot = warpReduceSum(tot);
    if (lane == 0) red[warp] = tot;
    __syncthreads();
    if (warp == 0) {
        float t = (lane < 8) ? red[lane] : 0.f;
        t = warpReduceSum(t);
        if (lane == 0) g_wscale[o] = rsqrtf(t * (1.f / (CIN * 9)));
    }
}

// ---------------- K3: demod scale g[b,o] ----------------
__global__ void k3_demod(const float* __restrict__ mag) {
    int o = blockIdx.x, b = blockIdx.y, tid = threadIdx.x;
    float acc = 0.f;
    for (int i = tid; i < CIN; i += 128) {
        float s = g_sn[b * CIN + i];
        acc += g_rawsq[o * CIN + i] * s * s;
    }
    __shared__ float red[4];
    int warp = tid >> 5, lane = tid & 31;
    acc = warpReduceSum(acc);
    if (lane == 0) red[warp] = acc;
    __syncthreads();
    if (tid == 0) {
        float t = red[0] + red[1] + red[2] + red[3];
        float wsc = g_wscale[o];
        float d = rsqrtf(wsc * wsc * t + 1e-8f);
        g_g[b * COUT + o] = d * wsc * rsqrtf(mag[0]);
    }
}

// ---------------- K0x: padded half2(x*sn), halo zeros baked in --------
// g_xh[(b*256+pair)][p], p in 42x42 padded map; pair = channels (2p, 2p+1)
__global__ void k0_prex(const float* __restrict__ x) {
    const size_t N = (size_t)B_ * 256 * XP_STRIDE;
    for (size_t e = (size_t)blockIdx.x * 256 + threadIdx.x; e < N;
         e += (size_t)gridDim.x * 256) {
        int p = (int)(e % XP_STRIDE);
        int mp = (int)(e / XP_STRIDE);
        int b = mp >> 8, pairIdx = mp & 255;
        int c0 = pairIdx * 2;
        int prg = p / 42, pc = p - prg * 42;
        int gr = prg - 2, gq = pc - 2;
        float v0 = 0.f, v1 = 0.f;
        if ((unsigned)gr < HS && (unsigned)gq < WS) {
            size_t sidx = (((size_t)b * CIN + c0) * HS + gr) * WS + gq;
            v0 = x[sidx] * g_sn[b * CIN + c0];
            v1 = x[sidx + (size_t)HS * WS] * g_sn[b * CIN + c0 + 1];
        }
        __half2 h = __floats2half2_rn(v0, v1);
        g_xh[e] = *(uint32_t*)&h;
    }
}

// ---------------- K0w: weights -> half2 mma layout -------------
// dst[ot][chunk][tap][o_local*8 + kpidx], kpidx = (kpl%4)*2 + kpl/4
// kpl = pair-in-chunk (0..7); u32 = half2(w[ch even], w[ch odd])
__global__ void k0_prew(const float* __restrict__ weight) {
    int e = blockIdx.x * 256 + threadIdx.x;
    const int N = COUT * 256 * 9;      // (o, global pair, tap)
    if (e >= N) return;
    int tap = e % 9;
    int r = e / 9;
    int kp = r & 255;                  // global channel pair 0..255
    int o = r >> 8;
    int chunk = kp >> 3, kpl = kp & 7;
    int kpidx = (kpl & 3) * 2 + (kpl >> 2);
    size_t s0 = ((size_t)o * CIN + kp * 2) * 9 + tap;
    __half2 h = __floats2half2_rn(weight[s0], weight[s0 + 9]);
    size_t dst = ((((size_t)(o >> 6) * 32 + chunk) * 9 + tap) * 512) + (o & 63) * 8 + kpidx;
    g_wh2[dst] = *(uint32_t*)&h;
}

// ---------------- K4: fp16 m16n8k16 conv, cp.async double-buffered ----
// grid = (8 o-tiles, 10 r-tiles of 4 rows, 16 b), block = 128 (4 warps), occ 4
// CTA: 64 Cout x (4 rows x 40 cols). Warp: 32 Cout (2 strips of 16) x 80 px.
// Finer tiles (1280) cut wave-quantization tail vs 640x256t version.
__global__ __launch_bounds__(128, 4) void k4_mma() {
    extern __shared__ uint32_t dsm[];
    const int b  = blockIdx.z;
    const int o0 = blockIdx.x * 64;
    const int r0 = blockIdx.y * 4;

    const int tid  = threadIdx.x;
    const int lane = tid & 31;
    const int wrp  = tid >> 5;
    const int ob   = (wrp & 1) * 32;    // warp o-offset
    const int pr0  = (wrp >> 1) * 2;    // warp row-offset (0,2)
    const int ln4  = lane >> 2;
    const int lk   = lane & 3;

    float c[2][10][4];
    #pragma unroll
    for (int s = 0; s < 2; s++)
        #pragma unroll
        for (int f = 0; f < 10; f++)
            #pragma unroll
            for (int j = 0; j < 4; j++) c[s][f][j] = 0.f;

    // x source: pair rows for chunk cc start at global pair b*256 + cc*8; tile base r0
    const uint32_t* xsrc = g_xh + (size_t)(b * 256) * XP_STRIDE + r0 * 42;
    const uint32_t* wsrc0 = g_wh2 + (size_t)blockIdx.x * 32 * 9 * 512;
    const uint32_t sbase = (uint32_t)__cvta_generic_to_shared(dsm);

    auto issue = [&](int chunk, int stage) {
        const uint32_t xs = sbase + (uint32_t)stage * (STAGE_U * 4);
        const uint32_t wsb = xs + XTILE_U * 4;
        const uint32_t* sx = xsrc + (size_t)chunk * 8 * XP_STRIDE;
        // x tile: 8 pair-rows x 252 u32 (6 rows x 42) = 504 float4s
        #pragma unroll
        for (int it = 0; it < 4; it++) {
            int e = tid + it * 128;
            if (e < 504) {
                int pr = e / 63, j = e - pr * 63;
                cp_async16(xs + (uint32_t)(pr * XT_S + 4 * j) * 4,
                           sx + (size_t)pr * XP_STRIDE + 4 * j);
            }
        }
        // w tile: 4608 u32 = 1152 float4s, layout matches smem
        const uint32_t* sw = wsrc0 + (size_t)chunk * (9 * 512);
        #pragma unroll
        for (int it = 0; it < 9; it++) {
            int e = tid + it * 128;
            cp_async16(wsb + (uint32_t)e * 16, sw + (size_t)e * 4);
        }
        asm volatile("cp.async.commit_group;");
    };

    issue(0, 0);
    issue(1, 1);

    for (int i = 0; i < 32; i++) {
        if (i < 30) asm volatile("cp.async.wait_group 1;");
        else        asm volatile("cp.async.wait_group 0;");
        __syncthreads();
        const uint32_t* xsm = dsm + (i & 1) * STAGE_U;
        const uint32_t* wsm = xsm + XTILE_U;

        // ---- compute: 9 taps x 10 frags x 2 o-strips, K=16/mma ----
        #pragma unroll
        for (int ky = 0; ky < 3; ky++) {
            #pragma unroll
            for (int kx = 0; kx < 3; kx++) {
                const int tap = ky * 3 + kx;
                uint2 a_lo[2], a_hi[2];
                #pragma unroll
                for (int s = 0; s < 2; s++) {
                    const uint32_t* wp = wsm + tap * 512 + (ob + s * 16 + ln4) * 8 + lk * 2;
                    a_lo[s] = *(const uint2*)wp;          // rows +0: (a0, a2)
                    a_hi[s] = *(const uint2*)(wp + 64);   // rows +8: (a1, a3)
                }
                #pragma unroll
                for (int f = 0; f < 10; f++) {
                    const int pr = pr0 + (f >= 5 ? 1 : 0);
                    const int cg = (f >= 5 ? f - 5 : f);
                    const int idx = (pr + ky) * 42 + cg * 8 + ln4 + kx;
                    uint32_t b0 = xsm[lk * XT_S + idx];          // pairs lk (ch 2lk,2lk+1)
                    uint32_t b1 = xsm[(lk + 4) * XT_S + idx];    // pairs lk+4 (ch 2lk+8,+9)
                    mma_f16(c[0][f], a_lo[0].x, a_hi[0].x, a_lo[0].y, a_hi[0].y, b0, b1);
                    mma_f16(c[1][f], a_lo[1].x, a_hi[1].x, a_lo[1].y, a_hi[1].y, b0, b1);
                }
            }
        }
        __syncthreads();
        if (i + 2 < 32) issue(i + 2, i & 1);
    }

    // ---- epilogue: scale + bias, store to g_a ----
    const int n0 = lk * 2;
    #pragma unroll
    for (int s = 0; s < 2; s++) {
        #pragma unroll
        for (int rh = 0; rh < 2; rh++) {
            const int o = o0 + ob + s * 16 + ln4 + rh * 8;
            const float gg = g_g[b * COUT + o];
            const float bb = g_bb[b * COUT + o];
            float* abase = g_a + ((size_t)(b * COUT + o)) * (HO * HO);
            #pragma unroll
            for (int f = 0; f < 10; f++) {
                const int r = r0 + pr0 + (f >= 5 ? 1 : 0);
                if (r >= HO) continue;
                const int cg = (f >= 5 ? f - 5 : f);
                const int q = cg * 8 + n0;
                float* ap = abase + r * HO;
                float v0 = c[s][f][rh * 2 + 0] * gg + bb;
                float v1 = c[s][f][rh * 2 + 1] * gg + bb;
                if (q < HO)     ap[q]     = v0;
                if (q + 1 < HO) ap[q + 1] = v1;
            }
        }
    }
}

// ---------------- K5: fused filtered_lrelu ----------------
#define SB_APAD 0
#define SB_VPAD (46 * 38)
#define SB_Z    (46 * 38 + 82 * 46)
#define SB_FU   (46 * 38 + 82 * 46 + 82 * 82)
#define SB_FD   (SB_FU + 12)
#define SB_TOT  (SB_FD + 12)   // 12268 floats = 49072 B

__global__ __launch_bounds__(256) void k5_flrelu(const float* __restrict__ fup,
                                                 const float* __restrict__ fdn,
                                                 float* __restrict__ out) {
    const int map = blockIdx.x;
    __shared__ float sb[SB_TOT];
    float* Apad = sb + SB_APAD;
    float* Vpad = sb + SB_VPAD;
    float* Z    = sb + SB_Z;
    float* T    = sb;
    float* fu   = sb + SB_FU;
    float* fd   = sb + SB_FD;
    int tid = threadIdx.x;
    if (tid < 12) { fu[tid] = fup[tid] * 2.f; fd[tid] = fdn[tid]; }
    for (int i = tid; i < SB_Z; i += 256) sb[i] = 0.f;
    __syncthreads();
    const float* ap = g_a + (size_t)map * HO * HO;
    for (int i = tid; i < HO * HO; i += 256) {
        int r = i / HO, q = i - r * HO;
        Apad[(r + 4) * 38 + q] = ap[i];
    }
    __syncthreads();
    for (int e = tid; e < 82 * 38; e += 256) {
        int u = e / 38, j = e - u * 38;
        int a0 = u >> 1, ph = u & 1;
        float acc = 0.f;
        #pragma unroll
        for (int sg = 0; sg < 6; sg++)
            acc += fu[2 * sg + ph] * Apad[(a0 + 5 - sg) * 38 + j];
        Vpad[u * 46 + (j + 4)] = acc;
    }
    __syncthreads();
    for (int e = tid; e < 82 * 82; e += 256) {
        int u = e / 82, xq = e - u * 82;
        int cq = xq >> 1, ph = xq & 1;
        float acc = 0.f;
        #pragma unroll
        for (int sg = 0; sg < 6; sg++)
            acc += fu[2 * sg + ph] * Vpad[u * 46 + (cq + 5 - sg)];
        acc = (acc >= 0.f) ? acc : 0.2f * acc;
        acc *= 1.4142135623730951f;
        acc = fminf(fmaxf(acc, -256.f), 256.f);
        Z[e] = acc;
    }
    __syncthreads();
    for (int e = tid; e < 36 * 82; e += 256) {
        int r = e / 82, xq = e - r * 82;
        float acc = 0.f;
        #pragma unroll
        for (int s = 0; s < 12; s++)
            acc += fd[s] * Z[(2 * r + 11 - s) * 82 + xq];
        T[e] = acc;
    }
    __syncthreads();
    float* op = out + (size_t)map * 36 * 36;
    for (int e = tid; e < 36 * 36; e += 256) {
        int r = e / 36, c = e - r * 36;
        float acc = 0.f;
        #pragma unroll
        for (int s = 0; s < 12; s++)
            acc += fd[s] * T[r * 82 + (2 * c + 11 - s)];
        op[e] = acc;
    }
}

// ---------------- launch ----------------
extern "C" void kernel_launch(void* const* d_in, const int* in_sizes, int n_in,
                              void* d_out, int out_size) {
    const float* x    = (const float*)d_in[0];
    const float* w    = (const float*)d_in[1];
    const float* msg  = (const float*)d_in[2];
    const float* aw   = (const float*)d_in[3];
    const float* ab   = (const float*)d_in[4];
    const float* wgt  = (const float*)d_in[5];
    const float* bias = (const float*)d_in[6];
    const float* msw  = (const float*)d_in[7];
    const float* mbw  = (const float*)d_in[8];
    const float* fup  = (const float*)d_in[9];
    const float* fdn  = (const float*)d_in[10];
    const float* mag  = (const float*)d_in[11];
    float* out = (float*)d_out;

    cudaFuncSetAttribute(k4_mma, cudaFuncAttributeMaxDynamicSharedMemorySize, K4_SMEM);

    k1_style<<<B_, 512>>>(w, msg, aw, ab, bias, msw, mbw);
    k2_wnorm<<<COUT, 256>>>(wgt);
    k3_demod<<<dim3(COUT, B_), 128>>>(mag);
    {
        int nw = COUT * 256 * 9;
        k0_prew<<<(nw + 255) / 256, 256>>>(wgt);
        k0_prex<<<8192, 256>>>(x);
    }
    k4_mma<<<dim3(8, 10, B_), 128, K4_SMEM>>>();
    k5_flrelu<<<B_ * COUT, 256>>>(fup, fdn, out);
}

// round 15
// speedup vs baseline: 6.1283x; 1.1652x over previous
#include <cuda_runtime.h>
#include <cuda_fp16.h>
#include <stdint.h>

#define B_   16
#define CIN  512
#define COUT 512
#define HS   36
#define WS   36
#define HO   38   // conv output spatial

#define XP_STRIDE 1764   // padded x map: 42 rows x 42 cols (halo -2..39), u32(half2) units
#define XT_S      264    // k4 x-tile pair-row stride in u32 (264 % 32 == 8 -> bank-safe)
#define XTILE_U   2112   // 8 pair-rows * XT_S (6 rows x 42 used per pair-row)
#define WTILE_U   4608   // 9 taps * 512 (64 o * 8 kpidx)
#define STAGE_U   (XTILE_U + WTILE_U)          // 6720 u32 per stage
#define K4_SMEM   (2 * STAGE_U * 4)            // 53760 bytes

// ---------------- device scratch (no allocation allowed) ----------------
__device__ float g_sn[B_ * CIN];
__device__ float g_bb[B_ * COUT];
__device__ float g_g[B_ * COUT];
__device__ float g_wscale[COUT];
__device__ float g_rawsq[COUT * CIN];
__device__ float g_a[(size_t)B_ * COUT * HO * HO];          // conv out + bias (47MB)
__device__ uint32_t g_xh[(size_t)B_ * 256 * XP_STRIDE];     // half2(x*sn) padded (28.9MB)
__device__ uint32_t g_wh2[(size_t)8 * 32 * 9 * 512];        // half2 weights, mma layout (4.7MB)

__inline__ __device__ float warpReduceSum(float v) {
    #pragma unroll
    for (int off = 16; off; off >>= 1) v += __shfl_xor_sync(0xffffffffu, v, off);
    return v;
}

__device__ __forceinline__ void mma_f16(float c[4], uint32_t a0, uint32_t a1,
                                        uint32_t a2, uint32_t a3,
                                        uint32_t b0, uint32_t b1) {
    asm volatile(
        "mma.sync.aligned.m16n8k16.row.col.f32.f16.f16.f32 "
        "{%0,%1,%2,%3}, {%4,%5,%6,%7}, {%8,%9}, {%0,%1,%2,%3};\n"
        : "+f"(c[0]), "+f"(c[1]), "+f"(c[2]), "+f"(c[3])
        : "r"(a0), "r"(a1), "r"(a2), "r"(a3), "r"(b0), "r"(b1));
}

__device__ __forceinline__ void cp_async16(uint32_t s, const void* g) {
    asm volatile("cp.async.cg.shared.global [%0], [%1], 16;" :: "r"(s), "l"(g));
}

// ---------------- K1: styles s, normalized sn, modulated bias bb --------
__global__ void k1_style(const float* __restrict__ w, const float* __restrict__ msg,
                         const float* __restrict__ aw, const float* __restrict__ ab,
                         const float* __restrict__ bias, const float* __restrict__ msw,
                         const float* __restrict__ mbw) {
    int b = blockIdx.x;
    __shared__ float wsh[CIN];
    __shared__ float msh[64];
    __shared__ float ssh[CIN];
    __shared__ float red[16];
    int tid = threadIdx.x;
    wsh[tid] = w[b * CIN + tid];
    if (tid < 64) msh[tid] = msg[b * 64 + tid];
    __syncthreads();
    int warp = tid >> 5, lane = tid & 31;
    #pragma unroll 1
    for (int ii = 0; ii < 32; ii++) {
        int i = warp * 32 + ii;
        const float* ar = aw + (size_t)i * CIN;
        float acc = 0.f;
        for (int j = lane; j < CIN; j += 32) acc += wsh[j] * ar[j];
        float accm = 0.f;
        for (int m = lane; m < 64; m += 32) accm += msh[m] * msw[m * CIN + i];
        float v = warpReduceSum(acc + 0.01f * accm);
        if (lane == 0) ssh[i] = v + ab[i];
    }
    __syncthreads();
    float sv = ssh[tid];
    float ss = warpReduceSum(sv * sv);
    if (lane == 0) red[warp] = ss;
    __syncthreads();
    if (warp == 0) {
        float t = (lane < 16) ? red[lane] : 0.f;
        t = warpReduceSum(t);
        if (lane == 0) red[0] = t;
    }
    __syncthreads();
    g_sn[b * CIN + tid] = sv * rsqrtf(red[0] * (1.f / CIN));
    float bacc = 0.f;
    #pragma unroll 8
    for (int m = 0; m < 64; m++) bacc += msh[m] * mbw[m * COUT + tid];
    g_bb[b * COUT + tid] = bias[tid] + 0.01f * bacc;
}

// ---------------- K2: weight norms ----------------
__global__ void k2_wnorm(const float* __restrict__ weight) {
    int o = blockIdx.x, tid = threadIdx.x;
    float tot = 0.f;
    for (int i = tid; i < CIN; i += 256) {
        const float* wp = weight + ((size_t)o * CIN + i) * 9;
        float sq = 0.f;
        #pragma unroll
        for (int k = 0; k < 9; k++) sq += wp[k] * wp[k];
        g_rawsq[o * CIN + i] = sq;
        tot += sq;
    }
    __shared__ float red[8];
    int warp = tid >> 5, lane = tid & 31;
    tot = warpReduceSum(tot);
    if (lane == 0) red[warp] = tot;
    __syncthreads();
    if (warp == 0) {
        float t = (lane < 8) ? red[lane] : 0.f;
        t = warpReduceSum(t);
        if (lane == 0) g_wscale[o] = rsqrtf(t * (1.f / (CIN * 9)));
    }
}

// ---------------- K3: demod scale g[b,o] ----------------
__global__ void k3_demod(const float* __restrict__ mag) {
    int o = blockIdx.x, b = blockIdx.y, tid = threadIdx.x;
    float acc = 0.f;
    for (int i = tid; i < CIN; i += 128) {
        float s = g_sn[b * CIN + i];
        acc += g_rawsq[o * CIN + i] * s * s;
    }
    __shared__ float red[4];
    int warp = tid >> 5, lane = tid & 31;
    acc = warpReduceSum(acc);
    if (lane == 0) red[warp] = acc;
    __syncthreads();
    if (tid == 0) {
        float t = red[0] + red[1] + red[2] + red[3];
        float wsc = g_wscale[o];
        float d = rsqrtf(wsc * wsc * t + 1e-8f);
        g_g[b * COUT + o] = d * wsc * rsqrtf(mag[0]);
    }
}

// ---------------- K0x: padded half2(x*sn), halo zeros baked in --------
__global__ void k0_prex(const float* __restrict__ x) {
    const size_t N = (size_t)B_ * 256 * XP_STRIDE;
    for (size_t e = (size_t)blockIdx.x * 256 + threadIdx.x; e < N;
         e += (size_t)gridDim.x * 256) {
        int p = (int)(e % XP_STRIDE);
        int mp = (int)(e / XP_STRIDE);
        int b = mp >> 8, pairIdx = mp & 255;
        int c0 = pairIdx * 2;
        int prg = p / 42, pc = p - prg * 42;
        int gr = prg - 2, gq = pc - 2;
        float v0 = 0.f, v1 = 0.f;
        if ((unsigned)gr < HS && (unsigned)gq < WS) {
            size_t sidx = (((size_t)b * CIN + c0) * HS + gr) * WS + gq;
            v0 = x[sidx] * g_sn[b * CIN + c0];
            v1 = x[sidx + (size_t)HS * WS] * g_sn[b * CIN + c0 + 1];
        }
        __half2 h = __floats2half2_rn(v0, v1);
        g_xh[e] = *(uint32_t*)&h;
    }
}

// ---------------- K0w: weights -> half2 mma layout -------------
__global__ void k0_prew(const float* __restrict__ weight) {
    int e = blockIdx.x * 256 + threadIdx.x;
    const int N = COUT * 256 * 9;      // (o, global pair, tap)
    if (e >= N) return;
    int tap = e % 9;
    int r = e / 9;
    int kp = r & 255;                  // global channel pair 0..255
    int o = r >> 8;
    int chunk = kp >> 3, kpl = kp & 7;
    int kpidx = (kpl & 3) * 2 + (kpl >> 2);
    size_t s0 = ((size_t)o * CIN + kp * 2) * 9 + tap;
    __half2 h = __floats2half2_rn(weight[s0], weight[s0 + 9]);
    size_t dst = ((((size_t)(o >> 6) * 32 + chunk) * 9 + tap) * 512) + (o & 63) * 8 + kpidx;
    g_wh2[dst] = *(uint32_t*)&h;
}

// ---------------- K4: fp16 m16n8k16 conv, cp.async double-buffered ----
// grid = (8 o-tiles, 10 r-tiles of 4 rows, 16 b), block = 128 (4 warps), occ 4
__global__ __launch_bounds__(128, 4) void k4_mma() {
    extern __shared__ uint32_t dsm[];
    const int b  = blockIdx.z;
    const int o0 = blockIdx.x * 64;
    const int r0 = blockIdx.y * 4;

    const int tid  = threadIdx.x;
    const int lane = tid & 31;
    const int wrp  = tid >> 5;
    const int ob   = (wrp & 1) * 32;    // warp o-offset
    const int pr0  = (wrp >> 1) * 2;    // warp row-offset (0,2)
    const int ln4  = lane >> 2;
    const int lk   = lane & 3;

    float c[2][10][4];
    #pragma unroll
    for (int s = 0; s < 2; s++)
        #pragma unroll
        for (int f = 0; f < 10; f++)
            #pragma unroll
            for (int j = 0; j < 4; j++) c[s][f][j] = 0.f;

    const uint32_t* xsrc = g_xh + (size_t)(b * 256) * XP_STRIDE + r0 * 42;
    const uint32_t* wsrc0 = g_wh2 + (size_t)blockIdx.x * 32 * 9 * 512;
    const uint32_t sbase = (uint32_t)__cvta_generic_to_shared(dsm);

    auto issue = [&](int chunk, int stage) {
        const uint32_t xs = sbase + (uint32_t)stage * (STAGE_U * 4);
        const uint32_t wsb = xs + XTILE_U * 4;
        const uint32_t* sx = xsrc + (size_t)chunk * 8 * XP_STRIDE;
        #pragma unroll
        for (int it = 0; it < 4; it++) {
            int e = tid + it * 128;
            if (e < 504) {
                int pr = e / 63, j = e - pr * 63;
                cp_async16(xs + (uint32_t)(pr * XT_S + 4 * j) * 4,
                           sx + (size_t)pr * XP_STRIDE + 4 * j);
            }
        }
        const uint32_t* sw = wsrc0 + (size_t)chunk * (9 * 512);
        #pragma unroll
        for (int it = 0; it < 9; it++) {
            int e = tid + it * 128;
            cp_async16(wsb + (uint32_t)e * 16, sw + (size_t)e * 4);
        }
        asm volatile("cp.async.commit_group;");
    };

    issue(0, 0);
    issue(1, 1);

    for (int i = 0; i < 32; i++) {
        if (i < 30) asm volatile("cp.async.wait_group 1;");
        else        asm volatile("cp.async.wait_group 0;");
        __syncthreads();
        const uint32_t* xsm = dsm + (i & 1) * STAGE_U;
        const uint32_t* wsm = xsm + XTILE_U;

        #pragma unroll
        for (int ky = 0; ky < 3; ky++) {
            #pragma unroll
            for (int kx = 0; kx < 3; kx++) {
                const int tap = ky * 3 + kx;
                uint2 a_lo[2], a_hi[2];
                #pragma unroll
                for (int s = 0; s < 2; s++) {
                    const uint32_t* wp = wsm + tap * 512 + (ob + s * 16 + ln4) * 8 + lk * 2;
                    a_lo[s] = *(const uint2*)wp;          // rows +0: (a0, a2)
                    a_hi[s] = *(const uint2*)(wp + 64);   // rows +8: (a1, a3)
                }
                #pragma unroll
                for (int f = 0; f < 10; f++) {
                    const int pr = pr0 + (f >= 5 ? 1 : 0);
                    const int cg = (f >= 5 ? f - 5 : f);
                    const int idx = (pr + ky) * 42 + cg * 8 + ln4 + kx;
                    uint32_t b0 = xsm[lk * XT_S + idx];
                    uint32_t b1 = xsm[(lk + 4) * XT_S + idx];
                    mma_f16(c[0][f], a_lo[0].x, a_hi[0].x, a_lo[0].y, a_hi[0].y, b0, b1);
                    mma_f16(c[1][f], a_lo[1].x, a_hi[1].x, a_lo[1].y, a_hi[1].y, b0, b1);
                }
            }
        }
        __syncthreads();
        if (i + 2 < 32) issue(i + 2, i & 1);
    }

    const int n0 = lk * 2;
    #pragma unroll
    for (int s = 0; s < 2; s++) {
        #pragma unroll
        for (int rh = 0; rh < 2; rh++) {
            const int o = o0 + ob + s * 16 + ln4 + rh * 8;
            const float gg = g_g[b * COUT + o];
            const float bb = g_bb[b * COUT + o];
            float* abase = g_a + ((size_t)(b * COUT + o)) * (HO * HO);
            #pragma unroll
            for (int f = 0; f < 10; f++) {
                const int r = r0 + pr0 + (f >= 5 ? 1 : 0);
                if (r >= HO) continue;
                const int cg = (f >= 5 ? f - 5 : f);
                const int q = cg * 8 + n0;
                float* ap = abase + r * HO;
                float v0 = c[s][f][rh * 2 + 0] * gg + bb;
                float v1 = c[s][f][rh * 2 + 1] * gg + bb;
                if (q < HO)     ap[q]     = v0;
                if (q + 1 < HO) ap[q + 1] = v1;
            }
        }
    }
}

// ---------------- K5: fused filtered_lrelu (register-windowed) ----------
// Same stage math/order as before (bit-identical outputs); each thread now
// loads a register window along the filter axis and computes a strip.
#define SB_APAD 0
#define SB_VPAD (46 * 38)
#define SB_Z    (46 * 38 + 82 * 46)
#define SB_TOT  (46 * 38 + 82 * 46 + 82 * 82)   // 12244 floats = 48976 B

__global__ __launch_bounds__(256) void k5_flrelu(const float* __restrict__ fup,
                                                 const float* __restrict__ fdn,
                                                 float* __restrict__ out) {
    const int map = blockIdx.x;
    __shared__ float sb[SB_TOT];
    float* Apad = sb + SB_APAD;   // 46 x 38
    float* Vpad = sb + SB_VPAD;   // 82 x 46
    float* Z    = sb + SB_Z;      // 82 x 82
    float* T    = sb;             // 36 x 82 (aliases Apad+Vpad, dead by then)
    const int tid = threadIdx.x;

    float fu[12], fd[12];
    #pragma unroll
    for (int s = 0; s < 12; s++) { fu[s] = fup[s] * 2.f; fd[s] = fdn[s]; }

    for (int i = tid; i < SB_Z; i += 256) sb[i] = 0.f;    // zero Apad+Vpad
    __syncthreads();
    const float* ap = g_a + (size_t)map * HO * HO;
    for (int i = tid; i < HO * HO; i += 256) {
        int r = i / HO, q = i - r * HO;
        Apad[(r + 4) * 38 + q] = ap[i];
    }
    __syncthreads();

    // ---- Vup: 228 threads, j = col, 14 u-rows per thread ----
    if (tid < 228) {
        const int j = tid % 38, ub = tid / 38;
        const int u0 = ub * 14;            // even
        const int a0 = u0 >> 1;
        float win[13];
        #pragma unroll
        for (int i = 0; i < 13; i++)
            win[i] = (a0 + i < 46) ? Apad[(a0 + i) * 38 + j] : 0.f;
        #pragma unroll
        for (int du = 0; du < 14; du++) {
            int u = u0 + du;
            if (u < 82) {
                const int ph = du & 1;
                float acc = 0.f;
                #pragma unroll
                for (int sg = 0; sg < 6; sg++)
                    acc += fu[2 * sg + ph] * win[(du >> 1) + 5 - sg];
                Vpad[u * 46 + (j + 4)] = acc;
            }
        }
    }
    __syncthreads();

    // ---- Hup + lrelu + clamp: 246 threads, u = row, 28 xq per thread ----
    if (tid < 246) {
        const int u = tid % 82, xb = tid / 82;
        const int x0 = xb * 28;            // even
        const int cb = x0 >> 1;
        float win[19];
        #pragma unroll
        for (int i = 0; i < 19; i++)
            win[i] = (cb + i < 46) ? Vpad[u * 46 + cb + i] : 0.f;
        #pragma unroll
        for (int dx = 0; dx < 28; dx++) {
            int xq = x0 + dx;
            if (xq < 82) {
                const int ph = dx & 1;
                float acc = 0.f;
                #pragma unroll
                for (int sg = 0; sg < 6; sg++)
                    acc += fu[2 * sg + ph] * win[(dx >> 1) + 5 - sg];
                acc = (acc >= 0.f) ? acc : 0.2f * acc;
                acc *= 1.4142135623730951f;
                acc = fminf(fmaxf(acc, -256.f), 256.f);
                Z[u * 82 + xq] = acc;
            }
        }
    }
    __syncthreads();

    // ---- Vdown: 246 threads, xq = col, 12 r per thread ----
    if (tid < 246) {
        const int xq = tid % 82, rb = tid / 82;
        const int r0 = rb * 12;
        const int z0 = 2 * r0;
        float wz[34];
        #pragma unroll
        for (int i = 0; i < 34; i++)
            wz[i] = Z[(z0 + i) * 82 + xq];
        #pragma unroll
        for (int dr = 0; dr < 12; dr++) {
            float acc = 0.f;
            #pragma unroll
            for (int s = 0; s < 12; s++)
                acc += fd[s] * wz[2 * dr + 11 - s];
            T[(r0 + dr) * 82 + xq] = acc;
        }
    }
    __syncthreads();

    // ---- Hdown: 216 threads, r = row, 6 c per thread ----
    if (tid < 216) {
        const int r = tid % 36, cbk = tid / 36;
        const int c0 = cbk * 6;
        float wt[22];
        #pragma unroll
        for (int i = 0; i < 22; i++)
            wt[i] = T[r * 82 + 2 * c0 + i];
        float* op = out + (size_t)map * 36 * 36 + r * 36;
        #pragma unroll
        for (int dc = 0; dc < 6; dc++) {
            float acc = 0.f;
            #pragma unroll
            for (int s = 0; s < 12; s++)
                acc += fd[s] * wt[2 * dc + 11 - s];
            op[c0 + dc] = acc;
        }
    }
}

// ---------------- launch ----------------
extern "C" void kernel_launch(void* const* d_in, const int* in_sizes, int n_in,
                              void* d_out, int out_size) {
    const float* x    = (const float*)d_in[0];
    const float* w    = (const float*)d_in[1];
    const float* msg  = (const float*)d_in[2];
    const float* aw   = (const float*)d_in[3];
    const float* ab   = (const float*)d_in[4];
    const float* wgt  = (const float*)d_in[5];
    const float* bias = (const float*)d_in[6];
    const float* msw  = (const float*)d_in[7];
    const float* mbw  = (const float*)d_in[8];
    const float* fup  = (const float*)d_in[9];
    const float* fdn  = (const float*)d_in[10];
    const float* mag  = (const float*)d_in[11];
    float* out = (float*)d_out;

    cudaFuncSetAttribute(k4_mma, cudaFuncAttributeMaxDynamicSharedMemorySize, K4_SMEM);

    k1_style<<<B_, 512>>>(w, msg, aw, ab, bias, msw, mbw);
    k2_wnorm<<<COUT, 256>>>(wgt);
    k3_demod<<<dim3(COUT, B_), 128>>>(mag);
    {
        int nw = COUT * 256 * 9;
        k0_prew<<<(nw + 255) / 256, 256>>>(wgt);
        k0_prex<<<8192, 256>>>(x);
    }
    k4_mma<<<dim3(8, 10, B_), 128, K4_SMEM>>>();
    k5_flrelu<<<B_ * COUT, 256>>>(fup, fdn, out);
}